// round 10
// baseline (speedup 1.0000x reference)
#include <cuda_runtime.h>
#include <cstdint>

// Problem constants
#define B_  4
#define S_  2048
#define D_  1024
#define H_  16
#define HD_ 64
#define M_  (B_*S_)   // 8192 rows

// Scratch (device globals — no allocation allowed)
__device__ float g_q[B_*H_*S_*HD_];   // [B,H,S,HD]
__device__ float g_k[B_*H_*S_*HD_];
__device__ float g_v[B_*H_*S_*HD_];
__device__ float g_ctx[(size_t)B_*S_*D_]; // [B,S,D]

// ---------------------------------------------------------------------------
// GEMM tile config: C[M,N] = A[M,K] * W[N,K]^T  (both K-major, row-major)
// 128x128 block tile, BK=16, 256 threads, 8x8 per-thread microtile with
// strided mapping (row = tm+16*i, col = tn+16*j) for conflict-free LDS.
// ---------------------------------------------------------------------------
#define BM 128
#define BN 128
#define BK 16

// Fused QKV projection: blockIdx.z in {0,1,2} selects (Wq->g_q, Wk->g_k, Wv->g_v).
// Epilogue permutes [m=b*S+s, n=h*HD+hd] -> [B,H,S,HD].
__global__ __launch_bounds__(256) void qkv_proj_kernel(
    const float* __restrict__ x,
    const float* __restrict__ Wq,
    const float* __restrict__ Wk,
    const float* __restrict__ Wv)
{
    const float* W   = (blockIdx.z == 0) ? Wq : (blockIdx.z == 1) ? Wk : Wv;
    float*       dst = (blockIdx.z == 0) ? g_q : (blockIdx.z == 1) ? g_k : g_v;

    __shared__ float As[BK][BM + 1];
    __shared__ float Bs[BK][BN + 1];

    const int tid = threadIdx.x;
    const int tm  = tid >> 4;   // 0..15
    const int tn  = tid & 15;   // 0..15
    const int m0  = blockIdx.y * BM;
    const int n0  = blockIdx.x * BN;

    float acc[8][8];
#pragma unroll
    for (int i = 0; i < 8; ++i)
#pragma unroll
        for (int j = 0; j < 8; ++j) acc[i][j] = 0.0f;

    for (int k0 = 0; k0 < D_; k0 += BK) {
#pragma unroll
        for (int l = 0; l < 2; ++l) {
            int idx = tid + l * 256;          // 0..511
            int r   = idx >> 2;               // 0..127
            int c4  = (idx & 3) << 2;         // 0,4,8,12
            float4 va = *(const float4*)(x + (size_t)(m0 + r) * D_ + k0 + c4);
            As[c4 + 0][r] = va.x; As[c4 + 1][r] = va.y;
            As[c4 + 2][r] = va.z; As[c4 + 3][r] = va.w;
            float4 vb = *(const float4*)(W + (size_t)(n0 + r) * D_ + k0 + c4);
            Bs[c4 + 0][r] = vb.x; Bs[c4 + 1][r] = vb.y;
            Bs[c4 + 2][r] = vb.z; Bs[c4 + 3][r] = vb.w;
        }
        __syncthreads();
#pragma unroll
        for (int k = 0; k < BK; ++k) {
            float a[8], b[8];
#pragma unroll
            for (int i = 0; i < 8; ++i) a[i] = As[k][tm + 16 * i];
#pragma unroll
            for (int j = 0; j < 8; ++j) b[j] = Bs[k][tn + 16 * j];
#pragma unroll
            for (int i = 0; i < 8; ++i)
#pragma unroll
                for (int j = 0; j < 8; ++j) acc[i][j] += a[i] * b[j];
        }
        __syncthreads();
    }

    // Permuted store: [B,H,S,HD]
#pragma unroll
    for (int i = 0; i < 8; ++i) {
        int m = m0 + tm + 16 * i;
        int b = m >> 11;            // / 2048
        int s = m & (S_ - 1);
#pragma unroll
        for (int j = 0; j < 8; ++j) {
            int n  = n0 + tn + 16 * j;
            int h  = n >> 6;
            int hd = n & 63;
            dst[(((size_t)(b * H_ + h)) * S_ + s) * HD_ + hd] = acc[i][j];
        }
    }
}

// Output projection: out[B,S,D] = ctx @ Wo^T (plain layout store)
__global__ __launch_bounds__(256) void oproj_kernel(
    const float* __restrict__ Wo,
    float* __restrict__ out)
{
    __shared__ float As[BK][BM + 1];
    __shared__ float Bs[BK][BN + 1];

    const int tid = threadIdx.x;
    const int tm  = tid >> 4;
    const int tn  = tid & 15;
    const int m0  = blockIdx.y * BM;
    const int n0  = blockIdx.x * BN;

    float acc[8][8];
#pragma unroll
    for (int i = 0; i < 8; ++i)
#pragma unroll
        for (int j = 0; j < 8; ++j) acc[i][j] = 0.0f;

    for (int k0 = 0; k0 < D_; k0 += BK) {
#pragma unroll
        for (int l = 0; l < 2; ++l) {
            int idx = tid + l * 256;
            int r   = idx >> 2;
            int c4  = (idx & 3) << 2;
            float4 va = *(const float4*)(g_ctx + (size_t)(m0 + r) * D_ + k0 + c4);
            As[c4 + 0][r] = va.x; As[c4 + 1][r] = va.y;
            As[c4 + 2][r] = va.z; As[c4 + 3][r] = va.w;
            float4 vb = *(const float4*)(Wo + (size_t)(n0 + r) * D_ + k0 + c4);
            Bs[c4 + 0][r] = vb.x; Bs[c4 + 1][r] = vb.y;
            Bs[c4 + 2][r] = vb.z; Bs[c4 + 3][r] = vb.w;
        }
        __syncthreads();
#pragma unroll
        for (int k = 0; k < BK; ++k) {
            float a[8], b[8];
#pragma unroll
            for (int i = 0; i < 8; ++i) a[i] = As[k][tm + 16 * i];
#pragma unroll
            for (int j = 0; j < 8; ++j) b[j] = Bs[k][tn + 16 * j];
#pragma unroll
            for (int i = 0; i < 8; ++i)
#pragma unroll
                for (int j = 0; j < 8; ++j) acc[i][j] += a[i] * b[j];
        }
        __syncthreads();
    }

#pragma unroll
    for (int i = 0; i < 8; ++i) {
        int m = m0 + tm + 16 * i;
#pragma unroll
        for (int j = 0; j < 8; ++j) {
            int n = n0 + tn + 16 * j;
            out[(size_t)m * D_ + n] = acc[i][j];
        }
    }
}

// ---------------------------------------------------------------------------
// Flash attention (fp32, causal). One block per (q-tile of 64 rows, b*h).
// 256 threads: ty=tid/16 owns rows {ty+16i}, tx=tid%16 owns cols {tx+16j}.
// smem: q_s[64][64], k_s[64][65] (reused for P), v_s[64][65]  -> 49664 B dyn.
// ---------------------------------------------------------------------------
#define QT 64
#define NEG_BIG (-1e30f)

__global__ __launch_bounds__(256) void attn_kernel()
{
    extern __shared__ float sm[];
    float* q_s = sm;                   // 64*64
    float* k_s = sm + 64 * 64;         // 64*65, reused as P
    float* v_s = k_s + 64 * 65;        // 64*65

    const int qt = blockIdx.x;         // 0..31
    const int bh = blockIdx.y;         // 0..63
    const float* Qg = g_q + (size_t)bh * S_ * HD_;
    const float* Kg = g_k + (size_t)bh * S_ * HD_;
    const float* Vg = g_v + (size_t)bh * S_ * HD_;

    const int tid = threadIdx.x;
    const int tx  = tid & 15;
    const int ty  = tid >> 4;

    // load Q tile (stride 64; reads are broadcast so no pad needed)
    for (int idx = tid; idx < QT * HD_; idx += 256) {
        int r = idx >> 6, c = idx & 63;
        q_s[r * 64 + c] = Qg[(size_t)(qt * QT + r) * HD_ + c];
    }

    float m_r[4], l_r[4], o[4][4];
#pragma unroll
    for (int i = 0; i < 4; ++i) {
        m_r[i] = NEG_BIG; l_r[i] = 0.0f;
#pragma unroll
        for (int j = 0; j < 4; ++j) o[i][j] = 0.0f;
    }

    for (int kt = 0; kt <= qt; ++kt) {
        __syncthreads();  // protect k_s (holds P of prev iter) + q_s on first iter
        for (int idx = tid; idx < QT * HD_; idx += 256) {
            int r = idx >> 6, c = idx & 63;
            k_s[r * 65 + c] = Kg[(size_t)(kt * QT + r) * HD_ + c];
            v_s[r * 65 + c] = Vg[(size_t)(kt * QT + r) * HD_ + c];
        }
        __syncthreads();

        // S = Q K^T  (each thread 4x4)
        float sv[4][4];
#pragma unroll
        for (int i = 0; i < 4; ++i)
#pragma unroll
            for (int j = 0; j < 4; ++j) sv[i][j] = 0.0f;

#pragma unroll 8
        for (int d = 0; d < HD_; ++d) {
            float qv[4], kv[4];
#pragma unroll
            for (int i = 0; i < 4; ++i) qv[i] = q_s[(ty + 16 * i) * 64 + d];
#pragma unroll
            for (int j = 0; j < 4; ++j) kv[j] = k_s[(tx + 16 * j) * 65 + d];
#pragma unroll
            for (int i = 0; i < 4; ++i)
#pragma unroll
                for (int j = 0; j < 4; ++j) sv[i][j] += qv[i] * kv[j];
        }

        const float sc = 0.125f;  // 1/sqrt(64)
        if (kt == qt) {
#pragma unroll
            for (int i = 0; i < 4; ++i)
#pragma unroll
                for (int j = 0; j < 4; ++j) {
                    int row = ty + 16 * i, col = tx + 16 * j;
                    sv[i][j] = (col > row) ? NEG_BIG : sv[i][j] * sc;
                }
        } else {
#pragma unroll
            for (int i = 0; i < 4; ++i)
#pragma unroll
                for (int j = 0; j < 4; ++j) sv[i][j] *= sc;
        }

        // row max across the 16 tx lanes (width-16 shfl segments)
        float mx[4];
#pragma unroll
        for (int i = 0; i < 4; ++i) {
            float v = fmaxf(fmaxf(sv[i][0], sv[i][1]), fmaxf(sv[i][2], sv[i][3]));
            mx[i] = v;
        }
#pragma unroll
        for (int off = 8; off; off >>= 1)
#pragma unroll
            for (int i = 0; i < 4; ++i)
                mx[i] = fmaxf(mx[i], __shfl_xor_sync(0xffffffffu, mx[i], off, 16));

        float al[4];
#pragma unroll
        for (int i = 0; i < 4; ++i) {
            float mn = fmaxf(m_r[i], mx[i]);
            al[i] = __expf(m_r[i] - mn);
            m_r[i] = mn;
        }

        float ps[4] = {0.f, 0.f, 0.f, 0.f};
#pragma unroll
        for (int i = 0; i < 4; ++i)
#pragma unroll
            for (int j = 0; j < 4; ++j) {
                float p = __expf(sv[i][j] - m_r[i]);
                sv[i][j] = p;
                ps[i] += p;
            }
#pragma unroll
        for (int off = 8; off; off >>= 1)
#pragma unroll
            for (int i = 0; i < 4; ++i)
                ps[i] += __shfl_xor_sync(0xffffffffu, ps[i], off, 16);

#pragma unroll
        for (int i = 0; i < 4; ++i) {
            l_r[i] = l_r[i] * al[i] + ps[i];
#pragma unroll
            for (int j = 0; j < 4; ++j) o[i][j] *= al[i];
        }

        __syncthreads();  // all threads done reading k_s -> safe to overwrite with P
#pragma unroll
        for (int i = 0; i < 4; ++i)
#pragma unroll
            for (int j = 0; j < 4; ++j)
                k_s[(ty + 16 * i) * 65 + (tx + 16 * j)] = sv[i][j];
        __syncthreads();

        // O += P V
#pragma unroll 8
        for (int k = 0; k < QT; ++k) {
            float pv[4], vv[4];
#pragma unroll
            for (int i = 0; i < 4; ++i) pv[i] = k_s[(ty + 16 * i) * 65 + k];
#pragma unroll
            for (int j = 0; j < 4; ++j) vv[j] = v_s[k * 65 + (tx + 16 * j)];
#pragma unroll
            for (int i = 0; i < 4; ++i)
#pragma unroll
                for (int j = 0; j < 4; ++j) o[i][j] += pv[i] * vv[j];
        }
    }

    // epilogue: ctx[b, s, h*64+c] = O / l
    const int b = bh >> 4;
    const int h = bh & 15;
#pragma unroll
    for (int i = 0; i < 4; ++i) {
        float inv = 1.0f / l_r[i];
        int srow = qt * QT + ty + 16 * i;
#pragma unroll
        for (int j = 0; j < 4; ++j) {
            int c = tx + 16 * j;
            g_ctx[((size_t)b * S_ + srow) * D_ + h * HD_ + c] = o[i][j] * inv;
        }
    }
}

// ---------------------------------------------------------------------------
// Launch
// ---------------------------------------------------------------------------
extern "C" void kernel_launch(void* const* d_in, const int* in_sizes, int n_in,
                              void* d_out, int out_size)
{
    const float* x  = (const float*)d_in[0];
    const float* Wq = (const float*)d_in[1];
    const float* Wk = (const float*)d_in[2];
    const float* Wv = (const float*)d_in[3];
    const float* Wo = (const float*)d_in[4];
    float* out = (float*)d_out;

    // 1) fused QKV projections (writes g_q/g_k/g_v in [B,H,S,HD])
    {
        dim3 grid(D_ / BN, M_ / BM, 3);
        qkv_proj_kernel<<<grid, 256>>>(x, Wq, Wk, Wv);
    }

    // 2) causal flash attention (writes g_ctx in [B,S,D])
    {
        const int smem_bytes = (64 * 64 + 2 * 64 * 65) * (int)sizeof(float); // 49664
        cudaFuncSetAttribute(attn_kernel,
                             cudaFuncAttributeMaxDynamicSharedMemorySize, smem_bytes);
        dim3 grid(S_ / QT, B_ * H_);
        attn_kernel<<<grid, 256, smem_bytes>>>();
    }

    // 3) output projection (writes d_out)
    {
        dim3 grid(D_ / BN, M_ / BM);
        oproj_kernel<<<grid, 256>>>(Wo, out);
    }
}

// round 11
// speedup vs baseline: 1.5400x; 1.5400x over previous
#include <cuda_runtime.h>
#include <cuda_bf16.h>
#include <cstdint>

// Problem constants
#define B_  4
#define S_  2048
#define D_  1024
#define H_  16
#define HD_ 64
#define M_  (B_*S_)   // 8192
#define K2  2048      // [hi | lo] split width
#define NKT 96        // 3072 / 32 k-tiles (3-term bf16 split)

// Scratch (device globals — no allocation allowed)
__device__ float g_q[B_*H_*S_*HD_];            // [B,H,S,HD] fp32
__device__ float g_k[B_*H_*S_*HD_];
__device__ float g_v[B_*H_*S_*HD_];
__device__ __nv_bfloat16 g_xs[(size_t)M_*K2];    // x split   [hi|lo]
__device__ __nv_bfloat16 g_ctxs[(size_t)M_*K2];  // ctx split [hi|lo]
__device__ __nv_bfloat16 g_ws[4][(size_t)D_*K2]; // Wq,Wk,Wv,Wo splits

// ---------------------------------------------------------------------------
// PTX helpers
// ---------------------------------------------------------------------------
__device__ __forceinline__ void cp_async16(uint32_t s, const void* g) {
    asm volatile("cp.async.cg.shared.global [%0], [%1], 16;\n" :: "r"(s), "l"(g));
}
__device__ __forceinline__ void cp_commit() {
    asm volatile("cp.async.commit_group;\n");
}
__device__ __forceinline__ void ldsm_x4(uint32_t* r, uint32_t addr) {
    asm volatile("ldmatrix.sync.aligned.m8n8.x4.shared.b16 {%0,%1,%2,%3}, [%4];\n"
        : "=r"(r[0]), "=r"(r[1]), "=r"(r[2]), "=r"(r[3]) : "r"(addr));
}
__device__ __forceinline__ void mma_bf16(float* c, const uint32_t* a, const uint32_t* b) {
    asm volatile("mma.sync.aligned.m16n8k16.row.col.f32.bf16.bf16.f32 "
        "{%0,%1,%2,%3}, {%4,%5,%6,%7}, {%8,%9}, {%0,%1,%2,%3};\n"
        : "+f"(c[0]), "+f"(c[1]), "+f"(c[2]), "+f"(c[3])
        : "r"(a[0]), "r"(a[1]), "r"(a[2]), "r"(a[3]), "r"(b[0]), "r"(b[1]));
}

// ---------------------------------------------------------------------------
// Split kernels: v -> (hi = bf16(v), lo = bf16(v - hi)) into [row][col] / [row][col+1024]
// ---------------------------------------------------------------------------
__device__ __forceinline__ void split4(float4 v, ushort4& hi, ushort4& lo) {
    __nv_bfloat16 h0 = __float2bfloat16(v.x);
    __nv_bfloat16 h1 = __float2bfloat16(v.y);
    __nv_bfloat16 h2 = __float2bfloat16(v.z);
    __nv_bfloat16 h3 = __float2bfloat16(v.w);
    __nv_bfloat16 l0 = __float2bfloat16(v.x - __bfloat162float(h0));
    __nv_bfloat16 l1 = __float2bfloat16(v.y - __bfloat162float(h1));
    __nv_bfloat16 l2 = __float2bfloat16(v.z - __bfloat162float(h2));
    __nv_bfloat16 l3 = __float2bfloat16(v.w - __bfloat162float(h3));
    hi = make_ushort4(__bfloat16_as_ushort(h0), __bfloat16_as_ushort(h1),
                      __bfloat16_as_ushort(h2), __bfloat16_as_ushort(h3));
    lo = make_ushort4(__bfloat16_as_ushort(l0), __bfloat16_as_ushort(l1),
                      __bfloat16_as_ushort(l2), __bfloat16_as_ushort(l3));
}

__global__ __launch_bounds__(256) void split_x_kernel(const float4* __restrict__ x4) {
    int i = blockIdx.x * 256 + threadIdx.x;     // quad index; total M_*D_/4
    float4 v = x4[i];
    int e0 = i << 2;
    int row = e0 >> 10;
    int col = e0 & 1023;
    ushort4 hi, lo;
    split4(v, hi, lo);
    *(ushort4*)&g_xs[(size_t)row * K2 + col]        = hi;
    *(ushort4*)&g_xs[(size_t)row * K2 + 1024 + col] = lo;
}

__global__ __launch_bounds__(256) void split_w_kernel(
    const float4* __restrict__ Wq4, const float4* __restrict__ Wk4,
    const float4* __restrict__ Wv4, const float4* __restrict__ Wo4)
{
    int which = blockIdx.y;
    const float4* src = (which == 0) ? Wq4 : (which == 1) ? Wk4 : (which == 2) ? Wv4 : Wo4;
    __nv_bfloat16* dst = g_ws[which];
    int i = blockIdx.x * 256 + threadIdx.x;     // quad index; total D_*D_/4
    float4 v = src[i];
    int e0 = i << 2;
    int row = e0 >> 10;
    int col = e0 & 1023;
    ushort4 hi, lo;
    split4(v, hi, lo);
    *(ushort4*)&dst[(size_t)row * K2 + col]        = hi;
    *(ushort4*)&dst[(size_t)row * K2 + 1024 + col] = lo;
}

// ---------------------------------------------------------------------------
// bf16-split MMA GEMM: C[M,N] = A[M,K]*W[N,K]^T with 3-term split (K_eff=3072)
// Block 128x128, BK=32, 256 threads (8 warps as 2m x 4n, warp tile 64x32).
// PERM: A=g_xs, W=g_ws[z], dst permuted into g_q/g_k/g_v [B,H,S,HD].
// else: A=g_ctxs, W=g_ws[3], dst = out [M,D].
// ---------------------------------------------------------------------------
#define SPITCH 40            // b16 pitch (32 data + 8 pad = 80B rows, conflict-free)
#define CH2    (64*SPITCH*2) // byte offset of second cp.async chunk (rows 64..127)

template<bool PERM>
__global__ __launch_bounds__(256, 2) void mma_gemm_kernel(float* __restrict__ outp)
{
    __shared__ __nv_bfloat16 smA[2][128 * SPITCH];
    __shared__ __nv_bfloat16 smB[2][128 * SPITCH];

    const __nv_bfloat16* A;
    const __nv_bfloat16* W;
    float* dst;
    if (PERM) {
        A = g_xs;
        W = g_ws[blockIdx.z];
        dst = (blockIdx.z == 0) ? g_q : (blockIdx.z == 1) ? g_k : g_v;
    } else {
        A = g_ctxs;
        W = g_ws[3];
        dst = outp;
    }

    const int tid  = threadIdx.x;
    const int lane = tid & 31;
    const int wid  = tid >> 5;
    const int wm   = wid & 1;    // 2 warps along M
    const int wn   = wid >> 1;   // 4 warps along N
    const int m0   = blockIdx.y * 128;
    const int n0   = blockIdx.x * 128;

    // cp.async chunk mapping: 512 chunks of 16B per operand tile; thread does tid, tid+256
    const int c0r = tid >> 2;           // rows 0..63 (second chunk: +64)
    const int c0c = (tid & 3) * 8;      // col offset in b16

    uint32_t stA[2], stB[2];
#pragma unroll
    for (int b = 0; b < 2; ++b) {
        stA[b] = (uint32_t)__cvta_generic_to_shared(&smA[b][c0r * SPITCH + c0c]);
        stB[b] = (uint32_t)__cvta_generic_to_shared(&smB[b][c0r * SPITCH + c0c]);
    }
    uint32_t smA_base[2], smB_base[2];
#pragma unroll
    for (int b = 0; b < 2; ++b) {
        smA_base[b] = (uint32_t)__cvta_generic_to_shared(&smA[b][0]);
        smB_base[b] = (uint32_t)__cvta_generic_to_shared(&smB[b][0]);
    }

    // ldmatrix lane addressing
    const int a_row = wm * 64 + (lane & 15);
    const int a_k   = (lane >> 4) * 8;
    const int b_row = wn * 32 + (lane & 7) + ((lane & 16) ? 8 : 0);
    const int b_k   = (lane & 8) ? 8 : 0;

    float acc[4][4][4];
#pragma unroll
    for (int mi = 0; mi < 4; ++mi)
#pragma unroll
        for (int nt = 0; nt < 4; ++nt)
#pragma unroll
            for (int r = 0; r < 4; ++r) acc[mi][nt][r] = 0.0f;

    auto issue = [&](int kt, int buf) {
        int seg  = kt >> 5;                 // 0: Ah*Wh, 1: Ah*Wl, 2: Al*Wh
        int koff = (kt & 31) * 32;
        int acol = koff + ((seg == 2) ? 1024 : 0);
        int wcol = koff + ((seg == 1) ? 1024 : 0);
        cp_async16(stA[buf],       A + (size_t)(m0 + c0r) * K2 + acol + c0c);
        cp_async16(stA[buf] + CH2, A + (size_t)(m0 + c0r + 64) * K2 + acol + c0c);
        cp_async16(stB[buf],       W + (size_t)(n0 + c0r) * K2 + wcol + c0c);
        cp_async16(stB[buf] + CH2, W + (size_t)(n0 + c0r + 64) * K2 + wcol + c0c);
        cp_commit();
    };

    issue(0, 0);
    for (int kt = 0; kt < NKT; ++kt) {
        int cur = kt & 1;
        if (kt + 1 < NKT) {
            issue(kt + 1, cur ^ 1);
            asm volatile("cp.async.wait_group 1;\n");
        } else {
            asm volatile("cp.async.wait_group 0;\n");
        }
        __syncthreads();

#pragma unroll
        for (int kk = 0; kk < 32; kk += 16) {
            uint32_t af[4][4], bfr[2][4];
#pragma unroll
            for (int mi = 0; mi < 4; ++mi)
                ldsm_x4(af[mi], smA_base[cur] + ((a_row + mi * 16) * SPITCH + kk + a_k) * 2);
#pragma unroll
            for (int np = 0; np < 2; ++np)
                ldsm_x4(bfr[np], smB_base[cur] + ((b_row + np * 16) * SPITCH + kk + b_k) * 2);
#pragma unroll
            for (int mi = 0; mi < 4; ++mi)
#pragma unroll
                for (int nt = 0; nt < 4; ++nt)
                    mma_bf16(acc[mi][nt], af[mi], &bfr[nt >> 1][(nt & 1) * 2]);
        }
        __syncthreads();
    }

    // Epilogue
    const int tr = lane >> 2;
    const int tc = (lane & 3) * 2;
#pragma unroll
    for (int mi = 0; mi < 4; ++mi) {
#pragma unroll
        for (int ni = 0; ni < 4; ++ni) {
            int r = m0 + wm * 64 + mi * 16 + tr;
            int c = n0 + wn * 32 + ni * 8 + tc;
#pragma unroll
            for (int half = 0; half < 2; ++half) {
                int m = r + half * 8;
                float v0 = acc[mi][ni][half * 2 + 0];
                float v1 = acc[mi][ni][half * 2 + 1];
                if (PERM) {
                    int b  = m >> 11;
                    int s  = m & (S_ - 1);
                    int hh = c >> 6;
                    int hd = c & 63;
                    *(float2*)&dst[(((size_t)(b * H_ + hh)) * S_ + s) * HD_ + hd] =
                        make_float2(v0, v1);
                } else {
                    *(float2*)&dst[(size_t)m * D_ + c] = make_float2(v0, v1);
                }
            }
        }
    }
}

// ---------------------------------------------------------------------------
// Flash attention (fp32, causal). One block per (64-row q-tile, b*h).
// Epilogue writes ctx directly as bf16 hi/lo split into g_ctxs.
// ---------------------------------------------------------------------------
#define QT 64
#define NEG_BIG (-1e30f)

__global__ __launch_bounds__(256) void attn_kernel()
{
    extern __shared__ float sm[];
    float* q_s = sm;                   // 64*64
    float* k_s = sm + 64 * 64;         // 64*65, reused as P
    float* v_s = k_s + 64 * 65;        // 64*65

    const int qt = blockIdx.x;
    const int bh = blockIdx.y;
    const float* Qg = g_q + (size_t)bh * S_ * HD_;
    const float* Kg = g_k + (size_t)bh * S_ * HD_;
    const float* Vg = g_v + (size_t)bh * S_ * HD_;

    const int tid = threadIdx.x;
    const int tx  = tid & 15;
    const int ty  = tid >> 4;

    for (int idx = tid; idx < QT * HD_; idx += 256) {
        int r = idx >> 6, c = idx & 63;
        q_s[r * 64 + c] = Qg[(size_t)(qt * QT + r) * HD_ + c];
    }

    float m_r[4], l_r[4], o[4][4];
#pragma unroll
    for (int i = 0; i < 4; ++i) {
        m_r[i] = NEG_BIG; l_r[i] = 0.0f;
#pragma unroll
        for (int j = 0; j < 4; ++j) o[i][j] = 0.0f;
    }

    for (int kt = 0; kt <= qt; ++kt) {
        __syncthreads();
        for (int idx = tid; idx < QT * HD_; idx += 256) {
            int r = idx >> 6, c = idx & 63;
            k_s[r * 65 + c] = Kg[(size_t)(kt * QT + r) * HD_ + c];
            v_s[r * 65 + c] = Vg[(size_t)(kt * QT + r) * HD_ + c];
        }
        __syncthreads();

        float sv[4][4];
#pragma unroll
        for (int i = 0; i < 4; ++i)
#pragma unroll
            for (int j = 0; j < 4; ++j) sv[i][j] = 0.0f;

#pragma unroll 8
        for (int d = 0; d < HD_; ++d) {
            float qv[4], kv[4];
#pragma unroll
            for (int i = 0; i < 4; ++i) qv[i] = q_s[(ty + 16 * i) * 64 + d];
#pragma unroll
            for (int j = 0; j < 4; ++j) kv[j] = k_s[(tx + 16 * j) * 65 + d];
#pragma unroll
            for (int i = 0; i < 4; ++i)
#pragma unroll
                for (int j = 0; j < 4; ++j) sv[i][j] += qv[i] * kv[j];
        }

        const float sc = 0.125f;
        if (kt == qt) {
#pragma unroll
            for (int i = 0; i < 4; ++i)
#pragma unroll
                for (int j = 0; j < 4; ++j) {
                    int row = ty + 16 * i, col = tx + 16 * j;
                    sv[i][j] = (col > row) ? NEG_BIG : sv[i][j] * sc;
                }
        } else {
#pragma unroll
            for (int i = 0; i < 4; ++i)
#pragma unroll
                for (int j = 0; j < 4; ++j) sv[i][j] *= sc;
        }

        float mx[4];
#pragma unroll
        for (int i = 0; i < 4; ++i)
            mx[i] = fmaxf(fmaxf(sv[i][0], sv[i][1]), fmaxf(sv[i][2], sv[i][3]));
#pragma unroll
        for (int off = 8; off; off >>= 1)
#pragma unroll
            for (int i = 0; i < 4; ++i)
                mx[i] = fmaxf(mx[i], __shfl_xor_sync(0xffffffffu, mx[i], off, 16));

        float al[4];
#pragma unroll
        for (int i = 0; i < 4; ++i) {
            float mn = fmaxf(m_r[i], mx[i]);
            al[i] = __expf(m_r[i] - mn);
            m_r[i] = mn;
        }

        float ps[4] = {0.f, 0.f, 0.f, 0.f};
#pragma unroll
        for (int i = 0; i < 4; ++i)
#pragma unroll
            for (int j = 0; j < 4; ++j) {
                float p = __expf(sv[i][j] - m_r[i]);
                sv[i][j] = p;
                ps[i] += p;
            }
#pragma unroll
        for (int off = 8; off; off >>= 1)
#pragma unroll
            for (int i = 0; i < 4; ++i)
                ps[i] += __shfl_xor_sync(0xffffffffu, ps[i], off, 16);

#pragma unroll
        for (int i = 0; i < 4; ++i) {
            l_r[i] = l_r[i] * al[i] + ps[i];
#pragma unroll
            for (int j = 0; j < 4; ++j) o[i][j] *= al[i];
        }

        __syncthreads();
#pragma unroll
        for (int i = 0; i < 4; ++i)
#pragma unroll
            for (int j = 0; j < 4; ++j)
                k_s[(ty + 16 * i) * 65 + (tx + 16 * j)] = sv[i][j];
        __syncthreads();

#pragma unroll 8
        for (int k = 0; k < QT; ++k) {
            float pv[4], vv[4];
#pragma unroll
            for (int i = 0; i < 4; ++i) pv[i] = k_s[(ty + 16 * i) * 65 + k];
#pragma unroll
            for (int j = 0; j < 4; ++j) vv[j] = v_s[k * 65 + (tx + 16 * j)];
#pragma unroll
            for (int i = 0; i < 4; ++i)
#pragma unroll
                for (int j = 0; j < 4; ++j) o[i][j] += pv[i] * vv[j];
        }
    }

    // epilogue: split ctx into bf16 hi/lo for the output projection
    const int bb = bh >> 4;
    const int hh = bh & 15;
#pragma unroll
    for (int i = 0; i < 4; ++i) {
        float inv = 1.0f / l_r[i];
        int srow = qt * QT + ty + 16 * i;
#pragma unroll
        for (int j = 0; j < 4; ++j) {
            int c = tx + 16 * j;
            float val = o[i][j] * inv;
            __nv_bfloat16 hi = __float2bfloat16(val);
            __nv_bfloat16 lo = __float2bfloat16(val - __bfloat162float(hi));
            size_t base = ((size_t)bb * S_ + srow) * K2 + hh * HD_ + c;
            g_ctxs[base]        = hi;
            g_ctxs[base + 1024] = lo;
        }
    }
}

// ---------------------------------------------------------------------------
// Launch
// ---------------------------------------------------------------------------
extern "C" void kernel_launch(void* const* d_in, const int* in_sizes, int n_in,
                              void* d_out, int out_size)
{
    const float* x  = (const float*)d_in[0];
    const float* Wq = (const float*)d_in[1];
    const float* Wk = (const float*)d_in[2];
    const float* Wv = (const float*)d_in[3];
    const float* Wo = (const float*)d_in[4];
    float* out = (float*)d_out;

    // 0) bf16 hi/lo splits of x and all weights
    split_x_kernel<<<(M_ * D_ / 4) / 256, 256>>>((const float4*)x);
    split_w_kernel<<<dim3((D_ * D_ / 4) / 256, 4), 256>>>(
        (const float4*)Wq, (const float4*)Wk, (const float4*)Wv, (const float4*)Wo);

    // 1) QKV projections on tensor cores (writes fp32 g_q/g_k/g_v in [B,H,S,HD])
    {
        dim3 grid(D_ / 128, M_ / 128, 3);
        mma_gemm_kernel<true><<<grid, 256>>>(nullptr);
    }

    // 2) causal flash attention (fp32; writes split ctx into g_ctxs)
    {
        const int smem_bytes = (64 * 64 + 2 * 64 * 65) * (int)sizeof(float);
        cudaFuncSetAttribute(attn_kernel,
                             cudaFuncAttributeMaxDynamicSharedMemorySize, smem_bytes);
        dim3 grid(S_ / QT, B_ * H_);
        attn_kernel<<<grid, 256, smem_bytes>>>();
    }

    // 3) output projection on tensor cores (writes d_out)
    {
        dim3 grid(D_ / 128, M_ / 128);
        mma_gemm_kernel<false><<<grid, 256>>>(out);
    }
}

// round 12
// speedup vs baseline: 3.0006x; 1.9485x over previous
#include <cuda_runtime.h>
#include <cuda_bf16.h>
#include <cuda_fp16.h>
#include <cstdint>

// Problem constants
#define B_  4
#define S_  2048
#define D_  1024
#define H_  16
#define HD_ 64
#define M_  (B_*S_)   // 8192
#define K2  2048      // [hi | lo] split width (bf16 GEMM path)
#define NKT 96        // 3072 / 32 k-tiles (3-term bf16 split)

#define CQ  0.1803368801111244f   // 0.125 * log2(e): folded into Q

// Scratch (device globals — no allocation allowed)
__device__ __half g_qh[(size_t)B_*H_*S_*HD_];   // Q*CQ hi  [B,H,S,64] fp16
__device__ __half g_ql[(size_t)B_*H_*S_*HD_];   // Q*CQ lo
__device__ __half g_kh[(size_t)B_*H_*S_*HD_];   // K hi
__device__ __half g_kl[(size_t)B_*H_*S_*HD_];   // K lo
__device__ __half g_vt[(size_t)B_*H_*80*S_];    // V^T [B,H,80,S]; row64=1, 65..79=0
__device__ __nv_bfloat16 g_xs[(size_t)M_*K2];    // x split   [hi|lo]
__device__ __nv_bfloat16 g_ctxs[(size_t)M_*K2];  // ctx split [hi|lo]
__device__ __nv_bfloat16 g_ws[4][(size_t)D_*K2]; // Wq,Wk,Wv,Wo splits

// ---------------------------------------------------------------------------
// PTX helpers
// ---------------------------------------------------------------------------
__device__ __forceinline__ void cp_async16(uint32_t s, const void* g) {
    asm volatile("cp.async.cg.shared.global [%0], [%1], 16;\n" :: "r"(s), "l"(g));
}
__device__ __forceinline__ void cp_commit() {
    asm volatile("cp.async.commit_group;\n");
}
__device__ __forceinline__ void ldsm_x4(uint32_t* r, uint32_t addr) {
    asm volatile("ldmatrix.sync.aligned.m8n8.x4.shared.b16 {%0,%1,%2,%3}, [%4];\n"
        : "=r"(r[0]), "=r"(r[1]), "=r"(r[2]), "=r"(r[3]) : "r"(addr));
}
__device__ __forceinline__ void mma_bf16(float* c, const uint32_t* a, const uint32_t* b) {
    asm volatile("mma.sync.aligned.m16n8k16.row.col.f32.bf16.bf16.f32 "
        "{%0,%1,%2,%3}, {%4,%5,%6,%7}, {%8,%9}, {%0,%1,%2,%3};\n"
        : "+f"(c[0]), "+f"(c[1]), "+f"(c[2]), "+f"(c[3])
        : "r"(a[0]), "r"(a[1]), "r"(a[2]), "r"(a[3]), "r"(b[0]), "r"(b[1]));
}
__device__ __forceinline__ void mma_f16(float* c, const uint32_t* a, const uint32_t* b) {
    asm volatile("mma.sync.aligned.m16n8k16.row.col.f32.f16.f16.f32 "
        "{%0,%1,%2,%3}, {%4,%5,%6,%7}, {%8,%9}, {%0,%1,%2,%3};\n"
        : "+f"(c[0]), "+f"(c[1]), "+f"(c[2]), "+f"(c[3])
        : "r"(a[0]), "r"(a[1]), "r"(a[2]), "r"(a[3]), "r"(b[0]), "r"(b[1]));
}
__device__ __forceinline__ float ex2f(float x) {
    float r;
    asm("ex2.approx.ftz.f32 %0, %1;" : "=f"(r) : "f"(x));
    return r;
}

// ---------------------------------------------------------------------------
// Split kernels (bf16 hi/lo for the projection GEMMs)
// ---------------------------------------------------------------------------
__device__ __forceinline__ void split4(float4 v, ushort4& hi, ushort4& lo) {
    __nv_bfloat16 h0 = __float2bfloat16(v.x);
    __nv_bfloat16 h1 = __float2bfloat16(v.y);
    __nv_bfloat16 h2 = __float2bfloat16(v.z);
    __nv_bfloat16 h3 = __float2bfloat16(v.w);
    __nv_bfloat16 l0 = __float2bfloat16(v.x - __bfloat162float(h0));
    __nv_bfloat16 l1 = __float2bfloat16(v.y - __bfloat162float(h1));
    __nv_bfloat16 l2 = __float2bfloat16(v.z - __bfloat162float(h2));
    __nv_bfloat16 l3 = __float2bfloat16(v.w - __bfloat162float(h3));
    hi = make_ushort4(__bfloat16_as_ushort(h0), __bfloat16_as_ushort(h1),
                      __bfloat16_as_ushort(h2), __bfloat16_as_ushort(h3));
    lo = make_ushort4(__bfloat16_as_ushort(l0), __bfloat16_as_ushort(l1),
                      __bfloat16_as_ushort(l2), __bfloat16_as_ushort(l3));
}

__global__ __launch_bounds__(256) void split_x_kernel(const float4* __restrict__ x4) {
    int i = blockIdx.x * 256 + threadIdx.x;
    float4 v = x4[i];
    int e0 = i << 2;
    int row = e0 >> 10;
    int col = e0 & 1023;
    ushort4 hi, lo;
    split4(v, hi, lo);
    *(ushort4*)&g_xs[(size_t)row * K2 + col]        = hi;
    *(ushort4*)&g_xs[(size_t)row * K2 + 1024 + col] = lo;
}

__global__ __launch_bounds__(256) void split_w_kernel(
    const float4* __restrict__ Wq4, const float4* __restrict__ Wk4,
    const float4* __restrict__ Wv4, const float4* __restrict__ Wo4)
{
    int which = blockIdx.y;
    const float4* src = (which == 0) ? Wq4 : (which == 1) ? Wk4 : (which == 2) ? Wv4 : Wo4;
    __nv_bfloat16* dst = g_ws[which];
    int i = blockIdx.x * 256 + threadIdx.x;
    float4 v = src[i];
    int e0 = i << 2;
    int row = e0 >> 10;
    int col = e0 & 1023;
    ushort4 hi, lo;
    split4(v, hi, lo);
    *(ushort4*)&dst[(size_t)row * K2 + col]        = hi;
    *(ushort4*)&dst[(size_t)row * K2 + 1024 + col] = lo;
}

// Fill g_vt pad rows: row 64 = 1.0 (l-accumulator column), rows 65..79 = 0.
__global__ __launch_bounds__(256) void vt_init_kernel() {
    size_t i = (size_t)blockIdx.x * 256 + threadIdx.x;  // 64 * 16 * 2048
    int bh  = (int)(i >> 15);
    int rem = (int)(i & 32767);
    int r   = rem >> 11;
    int s   = rem & 2047;
    g_vt[((size_t)bh * 80 + 64 + r) * S_ + s] = __float2half((r == 0) ? 1.0f : 0.0f);
}

// ---------------------------------------------------------------------------
// bf16-split MMA GEMM (verified in R11). PERM epilogue now emits fp16 Q/K
// splits and transposed fp16 V for the attention kernel.
// ---------------------------------------------------------------------------
#define SPITCH 40
#define CH2    (64*SPITCH*2)

template<bool PERM>
__global__ __launch_bounds__(256, 2) void mma_gemm_kernel(float* __restrict__ outp)
{
    __shared__ __nv_bfloat16 smA[2][128 * SPITCH];
    __shared__ __nv_bfloat16 smB[2][128 * SPITCH];

    const __nv_bfloat16* A;
    const __nv_bfloat16* W;
    if (PERM) { A = g_xs;   W = g_ws[blockIdx.z]; }
    else      { A = g_ctxs; W = g_ws[3]; }

    const int tid  = threadIdx.x;
    const int lane = tid & 31;
    const int wid  = tid >> 5;
    const int wm   = wid & 1;
    const int wn   = wid >> 1;
    const int m0   = blockIdx.y * 128;
    const int n0   = blockIdx.x * 128;

    const int c0r = tid >> 2;
    const int c0c = (tid & 3) * 8;

    uint32_t stA[2], stB[2], smA_base[2], smB_base[2];
#pragma unroll
    for (int b = 0; b < 2; ++b) {
        stA[b] = (uint32_t)__cvta_generic_to_shared(&smA[b][c0r * SPITCH + c0c]);
        stB[b] = (uint32_t)__cvta_generic_to_shared(&smB[b][c0r * SPITCH + c0c]);
        smA_base[b] = (uint32_t)__cvta_generic_to_shared(&smA[b][0]);
        smB_base[b] = (uint32_t)__cvta_generic_to_shared(&smB[b][0]);
    }

    const int a_row = wm * 64 + (lane & 15);
    const int a_k   = (lane >> 4) * 8;
    const int b_row = wn * 32 + (lane & 7) + ((lane & 16) ? 8 : 0);
    const int b_k   = (lane & 8) ? 8 : 0;

    float acc[4][4][4];
#pragma unroll
    for (int mi = 0; mi < 4; ++mi)
#pragma unroll
        for (int nt = 0; nt < 4; ++nt)
#pragma unroll
            for (int r = 0; r < 4; ++r) acc[mi][nt][r] = 0.0f;

    auto issue = [&](int kt, int buf) {
        int seg  = kt >> 5;
        int koff = (kt & 31) * 32;
        int acol = koff + ((seg == 2) ? 1024 : 0);
        int wcol = koff + ((seg == 1) ? 1024 : 0);
        cp_async16(stA[buf],       A + (size_t)(m0 + c0r) * K2 + acol + c0c);
        cp_async16(stA[buf] + CH2, A + (size_t)(m0 + c0r + 64) * K2 + acol + c0c);
        cp_async16(stB[buf],       W + (size_t)(n0 + c0r) * K2 + wcol + c0c);
        cp_async16(stB[buf] + CH2, W + (size_t)(n0 + c0r + 64) * K2 + wcol + c0c);
        cp_commit();
    };

    issue(0, 0);
    for (int kt = 0; kt < NKT; ++kt) {
        int cur = kt & 1;
        if (kt + 1 < NKT) {
            issue(kt + 1, cur ^ 1);
            asm volatile("cp.async.wait_group 1;\n");
        } else {
            asm volatile("cp.async.wait_group 0;\n");
        }
        __syncthreads();

#pragma unroll
        for (int kk = 0; kk < 32; kk += 16) {
            uint32_t af[4][4], bfr[2][4];
#pragma unroll
            for (int mi = 0; mi < 4; ++mi)
                ldsm_x4(af[mi], smA_base[cur] + ((a_row + mi * 16) * SPITCH + kk + a_k) * 2);
#pragma unroll
            for (int np = 0; np < 2; ++np)
                ldsm_x4(bfr[np], smB_base[cur] + ((b_row + np * 16) * SPITCH + kk + b_k) * 2);
#pragma unroll
            for (int mi = 0; mi < 4; ++mi)
#pragma unroll
                for (int nt = 0; nt < 4; ++nt)
                    mma_bf16(acc[mi][nt], af[mi], &bfr[nt >> 1][(nt & 1) * 2]);
        }
        __syncthreads();
    }

    const int tr = lane >> 2;
    const int tc = (lane & 3) * 2;
#pragma unroll
    for (int mi = 0; mi < 4; ++mi) {
#pragma unroll
        for (int ni = 0; ni < 4; ++ni) {
            int r = m0 + wm * 64 + mi * 16 + tr;
            int c = n0 + wn * 32 + ni * 8 + tc;
#pragma unroll
            for (int half_ = 0; half_ < 2; ++half_) {
                int m = r + half_ * 8;
                float v0 = acc[mi][ni][half_ * 2 + 0];
                float v1 = acc[mi][ni][half_ * 2 + 1];
                if (PERM) {
                    int b  = m >> 11;
                    int s  = m & (S_ - 1);
                    int hh = c >> 6;
                    int hd = c & 63;
                    size_t bh = (size_t)(b * H_ + hh);
                    if (blockIdx.z == 2) {
                        // V transposed: g_vt[bh][hd][s]
                        size_t base = (bh * 80 + hd) * S_ + s;
                        g_vt[base]      = __float2half_rn(v0);
                        g_vt[base + S_] = __float2half_rn(v1);
                    } else {
                        float u0 = v0, u1 = v1;
                        __half* dh;
                        __half* dl;
                        if (blockIdx.z == 0) {
                            u0 *= CQ; u1 *= CQ;
                            dh = g_qh; dl = g_ql;
                        } else {
                            dh = g_kh; dl = g_kl;
                        }
                        __half h0 = __float2half_rn(u0);
                        __half h1 = __float2half_rn(u1);
                        __half l0 = __float2half_rn(u0 - __half2float(h0));
                        __half l1 = __float2half_rn(u1 - __half2float(h1));
                        size_t idx = (bh * S_ + s) * 64 + hd;
                        *(__half2*)&dh[idx] = __halves2half2(h0, h1);
                        *(__half2*)&dl[idx] = __halves2half2(l0, l1);
                    }
                } else {
                    *(float2*)&outp[(size_t)m * D_ + c] = make_float2(v0, v1);
                }
            }
        }
    }
}

// ---------------------------------------------------------------------------
// MMA flash attention (causal). Block = (bh, 128-row q-tile); 8 warps x 16 rows.
// QK^T: 3-term fp16 split. PV: single fp16, with l as V^T ones-column (col 64).
// smem halves: Qh[128x72] Ql[128x72] Kh[64x72] Kl[64x72] Vt[80x72] P[128x72]
// ---------------------------------------------------------------------------
#define PITCH 72
#define QH_O  0
#define QL_O  (128*PITCH)
#define KH_O  (2*128*PITCH)
#define KL_O  (KH_O + 64*PITCH)
#define VT_O  (KL_O + 64*PITCH)
#define PS_O  (VT_O + 80*PITCH)
#define SM_HALVES (PS_O + 128*PITCH)   // 42624 halves = 85248 B

__global__ __launch_bounds__(256) void attn_mma_kernel()
{
    extern __shared__ __half sm[];
    const uint32_t sbase = (uint32_t)__cvta_generic_to_shared(sm);

    const int bh  = blockIdx.x;           // 0..63
    const int qt  = 15 - blockIdx.y;      // heavy tiles first
    const int q0  = qt * 128;
    const int tid = threadIdx.x;
    const int lane = tid & 31;
    const int wq   = tid >> 5;            // warp q-row group

    const __half* gQh = g_qh + (size_t)bh * S_ * 64;
    const __half* gQl = g_ql + (size_t)bh * S_ * 64;
    const __half* gKh = g_kh + (size_t)bh * S_ * 64;
    const __half* gKl = g_kl + (size_t)bh * S_ * 64;
    const __half* gVt = g_vt + (size_t)bh * 80 * S_;

    // load Q tile (hi+lo)
    for (int i = tid; i < 128 * 8; i += 256) {
        int r = i >> 3, ch = (i & 7) * 8;
        *(float4*)&sm[QH_O + r * PITCH + ch] = *(const float4*)&gQh[(size_t)(q0 + r) * 64 + ch];
        *(float4*)&sm[QL_O + r * PITCH + ch] = *(const float4*)&gQl[(size_t)(q0 + r) * 64 + ch];
    }

    float O[10][4];
#pragma unroll
    for (int f = 0; f < 10; ++f)
#pragma unroll
        for (int r = 0; r < 4; ++r) O[f][r] = 0.0f;
    float m0r = -1e30f, m1r = -1e30f;

    const int row0 = q0 + wq * 16 + (lane >> 2);
    const int row1 = row0 + 8;
    const int ccol = (lane & 3) * 2;

    const uint32_t aoff = ((wq * 16 + (lane & 15)) * PITCH + (lane >> 4) * 8) * 2;
    const int brow = (lane & 7) + ((lane & 16) ? 8 : 0);
    const int bk   = (lane & 8) ? 8 : 0;

    const int nkt = 2 * qt + 2;
    for (int kt = 0; kt < nkt; ++kt) {
        __syncthreads();
        for (int i = tid; i < 64 * 8; i += 256) {
            int r = i >> 3, ch = (i & 7) * 8;
            *(float4*)&sm[KH_O + r * PITCH + ch] = *(const float4*)&gKh[(size_t)(kt * 64 + r) * 64 + ch];
            *(float4*)&sm[KL_O + r * PITCH + ch] = *(const float4*)&gKl[(size_t)(kt * 64 + r) * 64 + ch];
        }
        for (int i = tid; i < 80 * 8; i += 256) {
            int r = i >> 3, ch = (i & 7) * 8;
            *(float4*)&sm[VT_O + r * PITCH + ch] = *(const float4*)&gVt[(size_t)r * S_ + kt * 64 + ch];
        }
        __syncthreads();

        if (kt * 64 > q0 + wq * 16 + 15) continue;   // whole warp masked

        // S = Qh*Kh + Qh*Kl + Ql*Kh  (scores in log2 domain, scale folded into Q)
        float S[8][4];
#pragma unroll
        for (int j = 0; j < 8; ++j)
#pragma unroll
            for (int r = 0; r < 4; ++r) S[j][r] = 0.0f;

#pragma unroll
        for (int kc = 0; kc < 4; ++kc) {
            uint32_t ah[4], al[4];
            ldsm_x4(ah, sbase + (QH_O)*2 + aoff + kc * 32);
            ldsm_x4(al, sbase + (QL_O)*2 + aoff + kc * 32);
#pragma unroll
            for (int np = 0; np < 4; ++np) {
                uint32_t bhf[4], blf[4];
                uint32_t boff = (uint32_t)(((np * 16 + brow) * PITCH + kc * 16 + bk) * 2);
                ldsm_x4(bhf, sbase + (KH_O)*2 + boff);
                ldsm_x4(blf, sbase + (KL_O)*2 + boff);
#pragma unroll
                for (int t = 0; t < 2; ++t) {
                    mma_f16(S[np * 2 + t], ah, &bhf[t * 2]);
                    mma_f16(S[np * 2 + t], ah, &blf[t * 2]);
                    mma_f16(S[np * 2 + t], al, &bhf[t * 2]);
                }
            }
        }

        // causal mask (diagonal tiles only)
        if (kt * 64 + 63 > q0 + wq * 16) {
#pragma unroll
            for (int j = 0; j < 8; ++j) {
                int c0 = kt * 64 + j * 8 + ccol;
                if (c0     > row0) S[j][0] = -30000.0f;
                if (c0 + 1 > row0) S[j][1] = -30000.0f;
                if (c0     > row1) S[j][2] = -30000.0f;
                if (c0 + 1 > row1) S[j][3] = -30000.0f;
            }
        }

        // row maxes (across 8 frags, then across the quad lanes)
        float mt0 = -1e30f, mt1 = -1e30f;
#pragma unroll
        for (int j = 0; j < 8; ++j) {
            mt0 = fmaxf(mt0, fmaxf(S[j][0], S[j][1]));
            mt1 = fmaxf(mt1, fmaxf(S[j][2], S[j][3]));
        }
#pragma unroll
        for (int off = 1; off <= 2; off <<= 1) {
            mt0 = fmaxf(mt0, __shfl_xor_sync(0xffffffffu, mt0, off));
            mt1 = fmaxf(mt1, __shfl_xor_sync(0xffffffffu, mt1, off));
        }
        float mn0 = fmaxf(m0r, mt0), mn1 = fmaxf(m1r, mt1);
        float a0 = ex2f(m0r - mn0), a1 = ex2f(m1r - mn1);
        m0r = mn0; m1r = mn1;
#pragma unroll
        for (int f = 0; f < 10; ++f) {
            O[f][0] *= a0; O[f][1] *= a0;
            O[f][2] *= a1; O[f][3] *= a1;
        }

        // P = exp2(S - m)  -> fp16 smem (each warp owns its 16 rows)
        const int prow = wq * 16 + (lane >> 2);
#pragma unroll
        for (int j = 0; j < 8; ++j) {
            float p0 = ex2f(S[j][0] - mn0), p1 = ex2f(S[j][1] - mn0);
            float p2 = ex2f(S[j][2] - mn1), p3 = ex2f(S[j][3] - mn1);
            int c = j * 8 + ccol;
            *(__half2*)&sm[PS_O + prow * PITCH + c]       = __floats2half2_rn(p0, p1);
            *(__half2*)&sm[PS_O + (prow + 8) * PITCH + c] = __floats2half2_rn(p2, p3);
        }
        __syncwarp();

        // O += P * V^T   (n = 80: cols 0..63 ctx, col 64 = l)
#pragma unroll
        for (int kc = 0; kc < 4; ++kc) {
            uint32_t ap[4];
            ldsm_x4(ap, sbase + (PS_O)*2 + aoff + kc * 32);
#pragma unroll
            for (int np = 0; np < 5; ++np) {
                uint32_t bv[4];
                ldsm_x4(bv, sbase + (VT_O)*2 +
                        (uint32_t)(((np * 16 + brow) * PITCH + kc * 16 + bk) * 2));
                mma_f16(O[np * 2 + 0], ap, &bv[0]);
                mma_f16(O[np * 2 + 1], ap, &bv[2]);
            }
        }
    }

    // epilogue: normalize by l (accum col 64) and emit bf16 hi/lo ctx split
    float l0 = __shfl_sync(0xffffffffu, O[8][0], lane & ~3);
    float l1 = __shfl_sync(0xffffffffu, O[8][2], lane & ~3);
    float i0 = 1.0f / l0, i1 = 1.0f / l1;
    const int b = bh >> 4, h = bh & 15;
#pragma unroll
    for (int j = 0; j < 8; ++j) {
        int c = h * 64 + j * 8 + ccol;
#pragma unroll
        for (int half_ = 0; half_ < 2; ++half_) {
            int srow = half_ ? row1 : row0;
            float v0 = O[j][half_ * 2 + 0] * (half_ ? i1 : i0);
            float v1 = O[j][half_ * 2 + 1] * (half_ ? i1 : i0);
            __nv_bfloat16 h0 = __float2bfloat16(v0);
            __nv_bfloat16 h1 = __float2bfloat16(v1);
            __nv_bfloat16 e0 = __float2bfloat16(v0 - __bfloat162float(h0));
            __nv_bfloat16 e1 = __float2bfloat16(v1 - __bfloat162float(h1));
            size_t idx = ((size_t)b * S_ + srow) * K2 + c;
            *(ushort2*)&g_ctxs[idx] =
                make_ushort2(__bfloat16_as_ushort(h0), __bfloat16_as_ushort(h1));
            *(ushort2*)&g_ctxs[idx + 1024] =
                make_ushort2(__bfloat16_as_ushort(e0), __bfloat16_as_ushort(e1));
        }
    }
}

// ---------------------------------------------------------------------------
// Launch
// ---------------------------------------------------------------------------
extern "C" void kernel_launch(void* const* d_in, const int* in_sizes, int n_in,
                              void* d_out, int out_size)
{
    const float* x  = (const float*)d_in[0];
    const float* Wq = (const float*)d_in[1];
    const float* Wk = (const float*)d_in[2];
    const float* Wv = (const float*)d_in[3];
    const float* Wo = (const float*)d_in[4];
    float* out = (float*)d_out;

    // 0) splits + V^T pad init
    split_x_kernel<<<(M_ * D_ / 4) / 256, 256>>>((const float4*)x);
    split_w_kernel<<<dim3((D_ * D_ / 4) / 256, 4), 256>>>(
        (const float4*)Wq, (const float4*)Wk, (const float4*)Wv, (const float4*)Wo);
    vt_init_kernel<<<(64 * 16 * 2048) / 256, 256>>>();

    // 1) QKV projections -> fp16 attention operands
    {
        dim3 grid(D_ / 128, M_ / 128, 3);
        mma_gemm_kernel<true><<<grid, 256>>>(nullptr);
    }

    // 2) MMA flash attention -> g_ctxs (bf16 split)
    {
        const int smem_bytes = SM_HALVES * 2;   // 85248
        cudaFuncSetAttribute(attn_mma_kernel,
                             cudaFuncAttributeMaxDynamicSharedMemorySize, smem_bytes);
        dim3 grid(B_ * H_, S_ / 128);
        attn_mma_kernel<<<grid, 256, smem_bytes>>>();
    }

    // 3) output projection -> d_out
    {
        dim3 grid(D_ / 128, M_ / 128);
        mma_gemm_kernel<false><<<grid, 256>>>(out);
    }
}

// round 14
// speedup vs baseline: 3.1763x; 1.0585x over previous
#include <cuda_runtime.h>
#include <cuda_bf16.h>
#include <cuda_fp16.h>
#include <cstdint>

// Problem constants
#define B_  4
#define S_  2048
#define D_  1024
#define H_  16
#define HD_ 64
#define M_  (B_*S_)   // 8192
#define K2  2048      // [hi | lo] split width (bf16 GEMM path)
#define NKT 96        // 3072 / 32 k-tiles (3-term bf16 split)

#define CQ  0.1803368801111244f   // 0.125 * log2(e): folded into Q

// Scratch (device globals — no allocation allowed)
__device__ __half g_qh[(size_t)B_*H_*S_*HD_];   // Q*CQ hi  [B,H,S,64] fp16
__device__ __half g_ql[(size_t)B_*H_*S_*HD_];   // Q*CQ lo
__device__ __half g_kh[(size_t)B_*H_*S_*HD_];   // K hi
__device__ __half g_kl[(size_t)B_*H_*S_*HD_];   // K lo
__device__ __half g_vt[(size_t)B_*H_*80*S_];    // V^T [B,H,80,S]; row64=1, 65..79=0
__device__ __nv_bfloat16 g_xs[(size_t)M_*K2];    // x split   [hi|lo]
__device__ __nv_bfloat16 g_ctxs[(size_t)M_*K2];  // ctx split [hi|lo]
__device__ __nv_bfloat16 g_ws[4][(size_t)D_*K2]; // Wq,Wk,Wv,Wo splits

// ---------------------------------------------------------------------------
// PTX helpers
// ---------------------------------------------------------------------------
__device__ __forceinline__ void cp_async16(uint32_t s, const void* g) {
    asm volatile("cp.async.cg.shared.global [%0], [%1], 16;\n" :: "r"(s), "l"(g));
}
__device__ __forceinline__ void cp_commit() {
    asm volatile("cp.async.commit_group;\n");
}
__device__ __forceinline__ void ldsm_x4(uint32_t* r, uint32_t addr) {
    asm volatile("ldmatrix.sync.aligned.m8n8.x4.shared.b16 {%0,%1,%2,%3}, [%4];\n"
        : "=r"(r[0]), "=r"(r[1]), "=r"(r[2]), "=r"(r[3]) : "r"(addr));
}
__device__ __forceinline__ void mma_bf16(float* c, const uint32_t* a, const uint32_t* b) {
    asm volatile("mma.sync.aligned.m16n8k16.row.col.f32.bf16.bf16.f32 "
        "{%0,%1,%2,%3}, {%4,%5,%6,%7}, {%8,%9}, {%0,%1,%2,%3};\n"
        : "+f"(c[0]), "+f"(c[1]), "+f"(c[2]), "+f"(c[3])
        : "r"(a[0]), "r"(a[1]), "r"(a[2]), "r"(a[3]), "r"(b[0]), "r"(b[1]));
}
__device__ __forceinline__ void mma_f16(float* c, const uint32_t* a, const uint32_t* b) {
    asm volatile("mma.sync.aligned.m16n8k16.row.col.f32.f16.f16.f32 "
        "{%0,%1,%2,%3}, {%4,%5,%6,%7}, {%8,%9}, {%0,%1,%2,%3};\n"
        : "+f"(c[0]), "+f"(c[1]), "+f"(c[2]), "+f"(c[3])
        : "r"(a[0]), "r"(a[1]), "r"(a[2]), "r"(a[3]), "r"(b[0]), "r"(b[1]));
}
__device__ __forceinline__ float ex2f(float x) {
    float r;
    asm("ex2.approx.ftz.f32 %0, %1;" : "=f"(r) : "f"(x));
    return r;
}

// ---------------------------------------------------------------------------
// Split kernels (bf16 hi/lo for the projection GEMMs)
// ---------------------------------------------------------------------------
__device__ __forceinline__ void split4(float4 v, ushort4& hi, ushort4& lo) {
    __nv_bfloat16 h0 = __float2bfloat16(v.x);
    __nv_bfloat16 h1 = __float2bfloat16(v.y);
    __nv_bfloat16 h2 = __float2bfloat16(v.z);
    __nv_bfloat16 h3 = __float2bfloat16(v.w);
    __nv_bfloat16 l0 = __float2bfloat16(v.x - __bfloat162float(h0));
    __nv_bfloat16 l1 = __float2bfloat16(v.y - __bfloat162float(h1));
    __nv_bfloat16 l2 = __float2bfloat16(v.z - __bfloat162float(h2));
    __nv_bfloat16 l3 = __float2bfloat16(v.w - __bfloat162float(h3));
    hi = make_ushort4(__bfloat16_as_ushort(h0), __bfloat16_as_ushort(h1),
                      __bfloat16_as_ushort(h2), __bfloat16_as_ushort(h3));
    lo = make_ushort4(__bfloat16_as_ushort(l0), __bfloat16_as_ushort(l1),
                      __bfloat16_as_ushort(l2), __bfloat16_as_ushort(l3));
}

__global__ __launch_bounds__(256) void split_x_kernel(const float4* __restrict__ x4) {
    int i = blockIdx.x * 256 + threadIdx.x;
    float4 v = x4[i];
    int e0 = i << 2;
    int row = e0 >> 10;
    int col = e0 & 1023;
    ushort4 hi, lo;
    split4(v, hi, lo);
    *(ushort4*)&g_xs[(size_t)row * K2 + col]        = hi;
    *(ushort4*)&g_xs[(size_t)row * K2 + 1024 + col] = lo;
}

__global__ __launch_bounds__(256) void split_w_kernel(
    const float4* __restrict__ Wq4, const float4* __restrict__ Wk4,
    const float4* __restrict__ Wv4, const float4* __restrict__ Wo4)
{
    int which = blockIdx.y;
    const float4* src = (which == 0) ? Wq4 : (which == 1) ? Wk4 : (which == 2) ? Wv4 : Wo4;
    __nv_bfloat16* dst = g_ws[which];
    int i = blockIdx.x * 256 + threadIdx.x;
    float4 v = src[i];
    int e0 = i << 2;
    int row = e0 >> 10;
    int col = e0 & 1023;
    ushort4 hi, lo;
    split4(v, hi, lo);
    *(ushort4*)&dst[(size_t)row * K2 + col]        = hi;
    *(ushort4*)&dst[(size_t)row * K2 + 1024 + col] = lo;
}

__global__ __launch_bounds__(256) void vt_init_kernel() {
    size_t i = (size_t)blockIdx.x * 256 + threadIdx.x;  // 64 * 16 * 2048
    int bh  = (int)(i >> 15);
    int rem = (int)(i & 32767);
    int r   = rem >> 11;
    int s   = rem & 2047;
    g_vt[((size_t)bh * 80 + 64 + r) * S_ + s] = __float2half((r == 0) ? 1.0f : 0.0f);
}

// ---------------------------------------------------------------------------
// bf16-split MMA GEMM, 4-stage cp.async pipeline, one barrier per stage.
// Block 128x128, BK=32, 256 threads (8 warps as 2m x 4n, warp tile 64x32).
// ---------------------------------------------------------------------------
#define SPITCH  40                // b16 pitch (32 data + 8 pad)
#define CH2     (64*SPITCH*2)     // byte offset of rows 64..127 chunk
#define ST      4                 // pipeline stages
#define STAGE_B (128*SPITCH*2)    // bytes per stage per operand = 10240
#define GEMM_SMEM (ST*STAGE_B*2)  // 81920 B

template<bool PERM>
__global__ __launch_bounds__(256, 2) void mma_gemm_kernel(float* __restrict__ outp)
{
    extern __shared__ __nv_bfloat16 dsm[];

    const __nv_bfloat16* A;
    const __nv_bfloat16* W;
    if (PERM) { A = g_xs;   W = g_ws[blockIdx.z]; }
    else      { A = g_ctxs; W = g_ws[3]; }

    const int tid  = threadIdx.x;
    const int lane = tid & 31;
    const int wid  = tid >> 5;
    const int wm   = wid & 1;
    const int wn   = wid >> 1;
    const int m0   = blockIdx.y * 128;
    const int n0   = blockIdx.x * 128;

    const int c0r = tid >> 2;           // rows 0..63 (second chunk: +64)
    const int c0c = (tid & 3) * 8;      // col offset in b16

    const uint32_t aS = (uint32_t)__cvta_generic_to_shared(dsm);
    const uint32_t bS = aS + ST * STAGE_B;
    const uint32_t stA0 = aS + (uint32_t)(c0r * SPITCH + c0c) * 2;
    const uint32_t stB0 = bS + (uint32_t)(c0r * SPITCH + c0c) * 2;

    const int a_row = wm * 64 + (lane & 15);
    const int a_k   = (lane >> 4) * 8;
    const int b_row = wn * 32 + (lane & 7) + ((lane & 16) ? 8 : 0);
    const int b_k   = (lane & 8) ? 8 : 0;

    float acc[4][4][4];
#pragma unroll
    for (int mi = 0; mi < 4; ++mi)
#pragma unroll
        for (int nt = 0; nt < 4; ++nt)
#pragma unroll
            for (int r = 0; r < 4; ++r) acc[mi][nt][r] = 0.0f;

    auto issue = [&](int kt, int buf) {
        int seg  = kt >> 5;                 // 0: Ah*Wh, 1: Ah*Wl, 2: Al*Wh
        int koff = (kt & 31) * 32;
        int acol = koff + ((seg == 2) ? 1024 : 0);
        int wcol = koff + ((seg == 1) ? 1024 : 0);
        uint32_t sa = stA0 + (uint32_t)buf * STAGE_B;
        uint32_t sb = stB0 + (uint32_t)buf * STAGE_B;
        cp_async16(sa,       A + (size_t)(m0 + c0r) * K2 + acol + c0c);
        cp_async16(sa + CH2, A + (size_t)(m0 + c0r + 64) * K2 + acol + c0c);
        cp_async16(sb,       W + (size_t)(n0 + c0r) * K2 + wcol + c0c);
        cp_async16(sb + CH2, W + (size_t)(n0 + c0r + 64) * K2 + wcol + c0c);
        cp_commit();
    };

    issue(0, 0);
    issue(1, 1);
    issue(2, 2);

    for (int kt = 0; kt < NKT; ++kt) {
        const int cur = kt & 3;
        // stage kt ready when <= (groups_in_flight - 1 - position) pending
        if (kt < NKT - 2)      asm volatile("cp.async.wait_group 2;\n");
        else if (kt == NKT-2)  asm volatile("cp.async.wait_group 1;\n");
        else                   asm volatile("cp.async.wait_group 0;\n");
        __syncthreads();   // publishes stage cur; also orders all reads of stage (kt-1)&3

        if (kt + 3 < NKT) issue(kt + 3, (kt + 3) & 3);

        const uint32_t smA_cur = aS + (uint32_t)cur * STAGE_B;
        const uint32_t smB_cur = bS + (uint32_t)cur * STAGE_B;
#pragma unroll
        for (int kk = 0; kk < 32; kk += 16) {
            uint32_t af[4][4], bfr[2][4];
#pragma unroll
            for (int mi = 0; mi < 4; ++mi)
                ldsm_x4(af[mi], smA_cur + ((a_row + mi * 16) * SPITCH + kk + a_k) * 2);
#pragma unroll
            for (int np = 0; np < 2; ++np)
                ldsm_x4(bfr[np], smB_cur + ((b_row + np * 16) * SPITCH + kk + b_k) * 2);
#pragma unroll
            for (int mi = 0; mi < 4; ++mi)
#pragma unroll
                for (int nt = 0; nt < 4; ++nt)
                    mma_bf16(acc[mi][nt], af[mi], &bfr[nt >> 1][(nt & 1) * 2]);
        }
    }

    // Epilogue
    const int tr = lane >> 2;
    const int tc = (lane & 3) * 2;
#pragma unroll
    for (int mi = 0; mi < 4; ++mi) {
#pragma unroll
        for (int ni = 0; ni < 4; ++ni) {
            int r = m0 + wm * 64 + mi * 16 + tr;
            int c = n0 + wn * 32 + ni * 8 + tc;
#pragma unroll
            for (int half_ = 0; half_ < 2; ++half_) {
                int m = r + half_ * 8;
                float v0 = acc[mi][ni][half_ * 2 + 0];
                float v1 = acc[mi][ni][half_ * 2 + 1];
                if (PERM) {
                    int b  = m >> 11;
                    int s  = m & (S_ - 1);
                    int hh = c >> 6;
                    int hd = c & 63;
                    size_t bh = (size_t)(b * H_ + hh);
                    if (blockIdx.z == 2) {
                        size_t base = (bh * 80 + hd) * S_ + s;
                        g_vt[base]      = __float2half_rn(v0);
                        g_vt[base + S_] = __float2half_rn(v1);
                    } else {
                        float u0 = v0, u1 = v1;
                        __half* dh;
                        __half* dl;
                        if (blockIdx.z == 0) {
                            u0 *= CQ; u1 *= CQ;
                            dh = g_qh; dl = g_ql;
                        } else {
                            dh = g_kh; dl = g_kl;
                        }
                        __half h0 = __float2half_rn(u0);
                        __half h1 = __float2half_rn(u1);
                        __half l0 = __float2half_rn(u0 - __half2float(h0));
                        __half l1 = __float2half_rn(u1 - __half2float(h1));
                        size_t idx = (bh * S_ + s) * 64 + hd;
                        *(__half2*)&dh[idx] = __halves2half2(h0, h1);
                        *(__half2*)&dl[idx] = __halves2half2(l0, l1);
                    }
                } else {
                    *(float2*)&outp[(size_t)m * D_ + c] = make_float2(v0, v1);
                }
            }
        }
    }
}

// ---------------------------------------------------------------------------
// MMA flash attention (unchanged from R12 — verified)
// ---------------------------------------------------------------------------
#define PITCH 72
#define QH_O  0
#define QL_O  (128*PITCH)
#define KH_O  (2*128*PITCH)
#define KL_O  (KH_O + 64*PITCH)
#define VT_O  (KL_O + 64*PITCH)
#define PS_O  (VT_O + 80*PITCH)
#define SM_HALVES (PS_O + 128*PITCH)

__global__ __launch_bounds__(256) void attn_mma_kernel()
{
    extern __shared__ __half sm[];
    const uint32_t sbase = (uint32_t)__cvta_generic_to_shared(sm);

    const int bh  = blockIdx.x;
    const int qt  = 15 - blockIdx.y;
    const int q0  = qt * 128;
    const int tid = threadIdx.x;
    const int lane = tid & 31;
    const int wq   = tid >> 5;

    const __half* gQh = g_qh + (size_t)bh * S_ * 64;
    const __half* gQl = g_ql + (size_t)bh * S_ * 64;
    const __half* gKh = g_kh + (size_t)bh * S_ * 64;
    const __half* gKl = g_kl + (size_t)bh * S_ * 64;
    const __half* gVt = g_vt + (size_t)bh * 80 * S_;

    for (int i = tid; i < 128 * 8; i += 256) {
        int r = i >> 3, ch = (i & 7) * 8;
        *(float4*)&sm[QH_O + r * PITCH + ch] = *(const float4*)&gQh[(size_t)(q0 + r) * 64 + ch];
        *(float4*)&sm[QL_O + r * PITCH + ch] = *(const float4*)&gQl[(size_t)(q0 + r) * 64 + ch];
    }

    float O[10][4];
#pragma unroll
    for (int f = 0; f < 10; ++f)
#pragma unroll
        for (int r = 0; r < 4; ++r) O[f][r] = 0.0f;
    float m0r = -1e30f, m1r = -1e30f;

    const int row0 = q0 + wq * 16 + (lane >> 2);
    const int row1 = row0 + 8;
    const int ccol = (lane & 3) * 2;

    const uint32_t aoff = ((wq * 16 + (lane & 15)) * PITCH + (lane >> 4) * 8) * 2;
    const int brow = (lane & 7) + ((lane & 16) ? 8 : 0);
    const int bk   = (lane & 8) ? 8 : 0;

    const int nkt = 2 * qt + 2;
    for (int kt = 0; kt < nkt; ++kt) {
        __syncthreads();
        for (int i = tid; i < 64 * 8; i += 256) {
            int r = i >> 3, ch = (i & 7) * 8;
            *(float4*)&sm[KH_O + r * PITCH + ch] = *(const float4*)&gKh[(size_t)(kt * 64 + r) * 64 + ch];
            *(float4*)&sm[KL_O + r * PITCH + ch] = *(const float4*)&gKl[(size_t)(kt * 64 + r) * 64 + ch];
        }
        for (int i = tid; i < 80 * 8; i += 256) {
            int r = i >> 3, ch = (i & 7) * 8;
            *(float4*)&sm[VT_O + r * PITCH + ch] = *(const float4*)&gVt[(size_t)r * S_ + kt * 64 + ch];
        }
        __syncthreads();

        if (kt * 64 > q0 + wq * 16 + 15) continue;

        float S[8][4];
#pragma unroll
        for (int j = 0; j < 8; ++j)
#pragma unroll
            for (int r = 0; r < 4; ++r) S[j][r] = 0.0f;

#pragma unroll
        for (int kc = 0; kc < 4; ++kc) {
            uint32_t ah[4], al[4];
            ldsm_x4(ah, sbase + (QH_O)*2 + aoff + kc * 32);
            ldsm_x4(al, sbase + (QL_O)*2 + aoff + kc * 32);
#pragma unroll
            for (int np = 0; np < 4; ++np) {
                uint32_t bhf[4], blf[4];
                uint32_t boff = (uint32_t)(((np * 16 + brow) * PITCH + kc * 16 + bk) * 2);
                ldsm_x4(bhf, sbase + (KH_O)*2 + boff);
                ldsm_x4(blf, sbase + (KL_O)*2 + boff);
#pragma unroll
                for (int t = 0; t < 2; ++t) {
                    mma_f16(S[np * 2 + t], ah, &bhf[t * 2]);
                    mma_f16(S[np * 2 + t], ah, &blf[t * 2]);
                    mma_f16(S[np * 2 + t], al, &bhf[t * 2]);
                }
            }
        }

        if (kt * 64 + 63 > q0 + wq * 16) {
#pragma unroll
            for (int j = 0; j < 8; ++j) {
                int c0 = kt * 64 + j * 8 + ccol;
                if (c0     > row0) S[j][0] = -30000.0f;
                if (c0 + 1 > row0) S[j][1] = -30000.0f;
                if (c0     > row1) S[j][2] = -30000.0f;
                if (c0 + 1 > row1) S[j][3] = -30000.0f;
            }
        }

        float mt0 = -1e30f, mt1 = -1e30f;
#pragma unroll
        for (int j = 0; j < 8; ++j) {
            mt0 = fmaxf(mt0, fmaxf(S[j][0], S[j][1]));
            mt1 = fmaxf(mt1, fmaxf(S[j][2], S[j][3]));
        }
#pragma unroll
        for (int off = 1; off <= 2; off <<= 1) {
            mt0 = fmaxf(mt0, __shfl_xor_sync(0xffffffffu, mt0, off));
            mt1 = fmaxf(mt1, __shfl_xor_sync(0xffffffffu, mt1, off));
        }
        float mn0 = fmaxf(m0r, mt0), mn1 = fmaxf(m1r, mt1);
        float a0 = ex2f(m0r - mn0), a1 = ex2f(m1r - mn1);
        m0r = mn0; m1r = mn1;
#pragma unroll
        for (int f = 0; f < 10; ++f) {
            O[f][0] *= a0; O[f][1] *= a0;
            O[f][2] *= a1; O[f][3] *= a1;
        }

        const int prow = wq * 16 + (lane >> 2);
#pragma unroll
        for (int j = 0; j < 8; ++j) {
            float p0 = ex2f(S[j][0] - mn0), p1 = ex2f(S[j][1] - mn0);
            float p2 = ex2f(S[j][2] - mn1), p3 = ex2f(S[j][3] - mn1);
            int c = j * 8 + ccol;
            *(__half2*)&sm[PS_O + prow * PITCH + c]       = __floats2half2_rn(p0, p1);
            *(__half2*)&sm[PS_O + (prow + 8) * PITCH + c] = __floats2half2_rn(p2, p3);
        }
        __syncwarp();

#pragma unroll
        for (int kc = 0; kc < 4; ++kc) {
            uint32_t ap[4];
            ldsm_x4(ap, sbase + (PS_O)*2 + aoff + kc * 32);
#pragma unroll
            for (int np = 0; np < 5; ++np) {
                uint32_t bv[4];
                ldsm_x4(bv, sbase + (VT_O)*2 +
                        (uint32_t)(((np * 16 + brow) * PITCH + kc * 16 + bk) * 2));
                mma_f16(O[np * 2 + 0], ap, &bv[0]);
                mma_f16(O[np * 2 + 1], ap, &bv[2]);
            }
        }
    }

    float l0 = __shfl_sync(0xffffffffu, O[8][0], lane & ~3);
    float l1 = __shfl_sync(0xffffffffu, O[8][2], lane & ~3);
    float i0 = 1.0f / l0, i1 = 1.0f / l1;
    const int b = bh >> 4, h = bh & 15;
#pragma unroll
    for (int j = 0; j < 8; ++j) {
        int c = h * 64 + j * 8 + ccol;
#pragma unroll
        for (int half_ = 0; half_ < 2; ++half_) {
            int srow = half_ ? row1 : row0;
            float v0 = O[j][half_ * 2 + 0] * (half_ ? i1 : i0);
            float v1 = O[j][half_ * 2 + 1] * (half_ ? i1 : i0);
            __nv_bfloat16 h0 = __float2bfloat16(v0);
            __nv_bfloat16 h1 = __float2bfloat16(v1);
            __nv_bfloat16 e0 = __float2bfloat16(v0 - __bfloat162float(h0));
            __nv_bfloat16 e1 = __float2bfloat16(v1 - __bfloat162float(h1));
            size_t idx = ((size_t)b * S_ + srow) * K2 + c;
            *(ushort2*)&g_ctxs[idx] =
                make_ushort2(__bfloat16_as_ushort(h0), __bfloat16_as_ushort(h1));
            *(ushort2*)&g_ctxs[idx + 1024] =
                make_ushort2(__bfloat16_as_ushort(e0), __bfloat16_as_ushort(e1));
        }
    }
}

// ---------------------------------------------------------------------------
// Launch
// ---------------------------------------------------------------------------
extern "C" void kernel_launch(void* const* d_in, const int* in_sizes, int n_in,
                              void* d_out, int out_size)
{
    const float* x  = (const float*)d_in[0];
    const float* Wq = (const float*)d_in[1];
    const float* Wk = (const float*)d_in[2];
    const float* Wv = (const float*)d_in[3];
    const float* Wo = (const float*)d_in[4];
    float* out = (float*)d_out;

    split_x_kernel<<<(M_ * D_ / 4) / 256, 256>>>((const float4*)x);
    split_w_kernel<<<dim3((D_ * D_ / 4) / 256, 4), 256>>>(
        (const float4*)Wq, (const float4*)Wk, (const float4*)Wv, (const float4*)Wo);
    vt_init_kernel<<<(64 * 16 * 2048) / 256, 256>>>();

    // 1) QKV projections (4-stage pipelined bf16-split MMA) -> fp16 operands
    {
        cudaFuncSetAttribute(mma_gemm_kernel<true>,
                             cudaFuncAttributeMaxDynamicSharedMemorySize, GEMM_SMEM);
        dim3 grid(D_ / 128, M_ / 128, 3);
        mma_gemm_kernel<true><<<grid, 256, GEMM_SMEM>>>(nullptr);
    }

    // 2) MMA flash attention -> g_ctxs (bf16 split)
    {
        const int smem_bytes = SM_HALVES * 2;
        cudaFuncSetAttribute(attn_mma_kernel,
                             cudaFuncAttributeMaxDynamicSharedMemorySize, smem_bytes);
        dim3 grid(B_ * H_, S_ / 128);
        attn_mma_kernel<<<grid, 256, smem_bytes>>>();
    }

    // 3) output projection -> d_out
    {
        cudaFuncSetAttribute(mma_gemm_kernel<false>,
                             cudaFuncAttributeMaxDynamicSharedMemorySize, GEMM_SMEM);
        dim3 grid(D_ / 128, M_ / 128);
        mma_gemm_kernel<false><<<grid, 256, GEMM_SMEM>>>(out);
    }
}

// round 15
// speedup vs baseline: 6.7782x; 2.1340x over previous
#include <cuda_runtime.h>
#include <cuda_bf16.h>
#include <cuda_fp16.h>
#include <cstdint>

// Problem constants
#define B_  4
#define S_  2048
#define D_  1024
#define H_  16
#define HD_ 64
#define M_  (B_*S_)   // 8192
#define NKT 32        // 1024 / 32 k-tiles (single fp16, no split)

#define CQ  0.1803368801111244f   // 0.125 * log2(e): folded into Q

// Scratch (device globals — no allocation allowed)
__device__ __half g_qh[(size_t)B_*H_*S_*HD_];   // Q*CQ  [B,H,S,64] fp16
__device__ __half g_kh[(size_t)B_*H_*S_*HD_];   // K     [B,H,S,64] fp16
__device__ __half g_vt[(size_t)B_*H_*80*S_];    // V^T [B,H,80,S]; row64=1, 65..79=0
__device__ __half g_xh[(size_t)M_*D_];          // x fp16
__device__ __half g_ctxh[(size_t)M_*D_];        // ctx fp16
__device__ __half g_wh[4][(size_t)D_*D_];       // Wq,Wk,Wv,Wo fp16

// ---------------------------------------------------------------------------
// PTX helpers
// ---------------------------------------------------------------------------
__device__ __forceinline__ void cp_async16(uint32_t s, const void* g) {
    asm volatile("cp.async.cg.shared.global [%0], [%1], 16;\n" :: "r"(s), "l"(g));
}
__device__ __forceinline__ void cp_commit() {
    asm volatile("cp.async.commit_group;\n");
}
__device__ __forceinline__ void ldsm_x4(uint32_t* r, uint32_t addr) {
    asm volatile("ldmatrix.sync.aligned.m8n8.x4.shared.b16 {%0,%1,%2,%3}, [%4];\n"
        : "=r"(r[0]), "=r"(r[1]), "=r"(r[2]), "=r"(r[3]) : "r"(addr));
}
__device__ __forceinline__ void mma_f16(float* c, const uint32_t* a, const uint32_t* b) {
    asm volatile("mma.sync.aligned.m16n8k16.row.col.f32.f16.f16.f32 "
        "{%0,%1,%2,%3}, {%4,%5,%6,%7}, {%8,%9}, {%0,%1,%2,%3};\n"
        : "+f"(c[0]), "+f"(c[1]), "+f"(c[2]), "+f"(c[3])
        : "r"(a[0]), "r"(a[1]), "r"(a[2]), "r"(a[3]), "r"(b[0]), "r"(b[1]));
}
__device__ __forceinline__ float ex2f(float x) {
    float r;
    asm("ex2.approx.ftz.f32 %0, %1;" : "=f"(r) : "f"(x));
    return r;
}

// ---------------------------------------------------------------------------
// Convert kernels: fp32 -> fp16 (linear layouts, no split)
// ---------------------------------------------------------------------------
__device__ __forceinline__ ushort4 cvt4(float4 v) {
    return make_ushort4(__half_as_ushort(__float2half_rn(v.x)),
                        __half_as_ushort(__float2half_rn(v.y)),
                        __half_as_ushort(__float2half_rn(v.z)),
                        __half_as_ushort(__float2half_rn(v.w)));
}

__global__ __launch_bounds__(256) void cvt_x_kernel(const float4* __restrict__ x4) {
    int i = blockIdx.x * 256 + threadIdx.x;     // quad index; total M_*D_/4
    *(ushort4*)&g_xh[(size_t)i * 4] = cvt4(x4[i]);
}

__global__ __launch_bounds__(256) void cvt_w_kernel(
    const float4* __restrict__ Wq4, const float4* __restrict__ Wk4,
    const float4* __restrict__ Wv4, const float4* __restrict__ Wo4)
{
    int which = blockIdx.y;
    const float4* src = (which == 0) ? Wq4 : (which == 1) ? Wk4 : (which == 2) ? Wv4 : Wo4;
    int i = blockIdx.x * 256 + threadIdx.x;     // quad index; total D_*D_/4
    *(ushort4*)&g_wh[which][(size_t)i * 4] = cvt4(src[i]);
}

__global__ __launch_bounds__(256) void vt_init_kernel() {
    size_t i = (size_t)blockIdx.x * 256 + threadIdx.x;  // 64 * 16 * 2048
    int bh  = (int)(i >> 15);
    int rem = (int)(i & 32767);
    int r   = rem >> 11;
    int s   = rem & 2047;
    g_vt[((size_t)bh * 80 + 64 + r) * S_ + s] = __float2half((r == 0) ? 1.0f : 0.0f);
}

// ---------------------------------------------------------------------------
// fp16 MMA GEMM: C[M,N] = A[M,K]*W[N,K]^T, K=1024. 4-stage cp.async pipeline,
// one barrier per stage. Block 128x128, BK=32, 256 threads (2m x 4n warps).
// ---------------------------------------------------------------------------
#define SPITCH  40                // b16 pitch (32 data + 8 pad)
#define CH2     (64*SPITCH*2)     // byte offset of rows 64..127 chunk
#define ST      4                 // pipeline stages
#define STAGE_B (128*SPITCH*2)    // bytes per stage per operand = 10240
#define GEMM_SMEM (ST*STAGE_B*2)  // 81920 B

template<bool PERM>
__global__ __launch_bounds__(256, 2) void mma_gemm_kernel(float* __restrict__ outp)
{
    extern __shared__ __half dsm[];

    const __half* A;
    const __half* W;
    if (PERM) { A = g_xh;   W = g_wh[blockIdx.z]; }
    else      { A = g_ctxh; W = g_wh[3]; }

    const int tid  = threadIdx.x;
    const int lane = tid & 31;
    const int wid  = tid >> 5;
    const int wm   = wid & 1;
    const int wn   = wid >> 1;
    const int m0   = blockIdx.y * 128;
    const int n0   = blockIdx.x * 128;

    const int c0r = tid >> 2;           // rows 0..63 (second chunk: +64)
    const int c0c = (tid & 3) * 8;      // col offset in halves

    const uint32_t aS = (uint32_t)__cvta_generic_to_shared(dsm);
    const uint32_t bS = aS + ST * STAGE_B;
    const uint32_t stA0 = aS + (uint32_t)(c0r * SPITCH + c0c) * 2;
    const uint32_t stB0 = bS + (uint32_t)(c0r * SPITCH + c0c) * 2;

    const int a_row = wm * 64 + (lane & 15);
    const int a_k   = (lane >> 4) * 8;
    const int b_row = wn * 32 + (lane & 7) + ((lane & 16) ? 8 : 0);
    const int b_k   = (lane & 8) ? 8 : 0;

    float acc[4][4][4];
#pragma unroll
    for (int mi = 0; mi < 4; ++mi)
#pragma unroll
        for (int nt = 0; nt < 4; ++nt)
#pragma unroll
            for (int r = 0; r < 4; ++r) acc[mi][nt][r] = 0.0f;

    auto issue = [&](int kt, int buf) {
        int koff = kt * 32;
        uint32_t sa = stA0 + (uint32_t)buf * STAGE_B;
        uint32_t sb = stB0 + (uint32_t)buf * STAGE_B;
        cp_async16(sa,       A + (size_t)(m0 + c0r) * D_ + koff + c0c);
        cp_async16(sa + CH2, A + (size_t)(m0 + c0r + 64) * D_ + koff + c0c);
        cp_async16(sb,       W + (size_t)(n0 + c0r) * D_ + koff + c0c);
        cp_async16(sb + CH2, W + (size_t)(n0 + c0r + 64) * D_ + koff + c0c);
        cp_commit();
    };

    issue(0, 0);
    issue(1, 1);
    issue(2, 2);

    for (int kt = 0; kt < NKT; ++kt) {
        const int cur = kt & 3;
        if (kt < NKT - 2)      asm volatile("cp.async.wait_group 2;\n");
        else if (kt == NKT-2)  asm volatile("cp.async.wait_group 1;\n");
        else                   asm volatile("cp.async.wait_group 0;\n");
        __syncthreads();   // publishes stage cur; orders reads of stage (kt-1)&3

        if (kt + 3 < NKT) issue(kt + 3, (kt + 3) & 3);

        const uint32_t smA_cur = aS + (uint32_t)cur * STAGE_B;
        const uint32_t smB_cur = bS + (uint32_t)cur * STAGE_B;
#pragma unroll
        for (int kk = 0; kk < 32; kk += 16) {
            uint32_t af[4][4], bfr[2][4];
#pragma unroll
            for (int mi = 0; mi < 4; ++mi)
                ldsm_x4(af[mi], smA_cur + ((a_row + mi * 16) * SPITCH + kk + a_k) * 2);
#pragma unroll
            for (int np = 0; np < 2; ++np)
                ldsm_x4(bfr[np], smB_cur + ((b_row + np * 16) * SPITCH + kk + b_k) * 2);
#pragma unroll
            for (int mi = 0; mi < 4; ++mi)
#pragma unroll
                for (int nt = 0; nt < 4; ++nt)
                    mma_f16(acc[mi][nt], af[mi], &bfr[nt >> 1][(nt & 1) * 2]);
        }
    }

    // Epilogue
    const int tr = lane >> 2;
    const int tc = (lane & 3) * 2;
#pragma unroll
    for (int mi = 0; mi < 4; ++mi) {
#pragma unroll
        for (int ni = 0; ni < 4; ++ni) {
            int r = m0 + wm * 64 + mi * 16 + tr;
            int c = n0 + wn * 32 + ni * 8 + tc;
#pragma unroll
            for (int half_ = 0; half_ < 2; ++half_) {
                int m = r + half_ * 8;
                float v0 = acc[mi][ni][half_ * 2 + 0];
                float v1 = acc[mi][ni][half_ * 2 + 1];
                if (PERM) {
                    int b  = m >> 11;
                    int s  = m & (S_ - 1);
                    int hh = c >> 6;
                    int hd = c & 63;
                    size_t bh = (size_t)(b * H_ + hh);
                    if (blockIdx.z == 2) {
                        size_t base = (bh * 80 + hd) * S_ + s;
                        g_vt[base]      = __float2half_rn(v0);
                        g_vt[base + S_] = __float2half_rn(v1);
                    } else {
                        __half* dh = (blockIdx.z == 0) ? g_qh : g_kh;
                        if (blockIdx.z == 0) { v0 *= CQ; v1 *= CQ; }
                        size_t idx = (bh * S_ + s) * 64 + hd;
                        *(__half2*)&dh[idx] = __floats2half2_rn(v0, v1);
                    }
                } else {
                    *(float2*)&outp[(size_t)m * D_ + c] = make_float2(v0, v1);
                }
            }
        }
    }
}

// ---------------------------------------------------------------------------
// MMA flash attention (causal). Block = (bh, 128-row q-tile); 8 warps x 16 rows.
// Single fp16 QK^T; PV fp16 with l as V^T ones-column (col 64).
// smem halves: Qh[128x72] Kh[64x72] Vt[80x72] P[128x72] = 28800 (57.6 KB)
// ---------------------------------------------------------------------------
#define PITCH 72
#define QH_O  0
#define KH_O  (128*PITCH)
#define VT_O  (KH_O + 64*PITCH)
#define PS_O  (VT_O + 80*PITCH)
#define SM_HALVES (PS_O + 128*PITCH)

__global__ __launch_bounds__(256, 2) void attn_mma_kernel()
{
    extern __shared__ __half sm[];
    const uint32_t sbase = (uint32_t)__cvta_generic_to_shared(sm);

    const int bh  = blockIdx.x;
    const int qt  = 15 - blockIdx.y;      // heavy tiles first
    const int q0  = qt * 128;
    const int tid = threadIdx.x;
    const int lane = tid & 31;
    const int wq   = tid >> 5;

    const __half* gQh = g_qh + (size_t)bh * S_ * 64;
    const __half* gKh = g_kh + (size_t)bh * S_ * 64;
    const __half* gVt = g_vt + (size_t)bh * 80 * S_;

    for (int i = tid; i < 128 * 8; i += 256) {
        int r = i >> 3, ch = (i & 7) * 8;
        *(float4*)&sm[QH_O + r * PITCH + ch] = *(const float4*)&gQh[(size_t)(q0 + r) * 64 + ch];
    }

    float O[10][4];
#pragma unroll
    for (int f = 0; f < 10; ++f)
#pragma unroll
        for (int r = 0; r < 4; ++r) O[f][r] = 0.0f;
    float m0r = -1e30f, m1r = -1e30f;

    const int row0 = q0 + wq * 16 + (lane >> 2);
    const int row1 = row0 + 8;
    const int ccol = (lane & 3) * 2;

    const uint32_t aoff = ((wq * 16 + (lane & 15)) * PITCH + (lane >> 4) * 8) * 2;
    const int brow = (lane & 7) + ((lane & 16) ? 8 : 0);
    const int bk   = (lane & 8) ? 8 : 0;

    const int nkt = 2 * qt + 2;
    for (int kt = 0; kt < nkt; ++kt) {
        __syncthreads();
        for (int i = tid; i < 64 * 8; i += 256) {
            int r = i >> 3, ch = (i & 7) * 8;
            *(float4*)&sm[KH_O + r * PITCH + ch] = *(const float4*)&gKh[(size_t)(kt * 64 + r) * 64 + ch];
        }
        for (int i = tid; i < 80 * 8; i += 256) {
            int r = i >> 3, ch = (i & 7) * 8;
            *(float4*)&sm[VT_O + r * PITCH + ch] = *(const float4*)&gVt[(size_t)r * S_ + kt * 64 + ch];
        }
        __syncthreads();

        if (kt * 64 > q0 + wq * 16 + 15) continue;   // whole warp masked

        // S = Q K^T  (log2 domain; scale folded into Q)
        float S[8][4];
#pragma unroll
        for (int j = 0; j < 8; ++j)
#pragma unroll
            for (int r = 0; r < 4; ++r) S[j][r] = 0.0f;

#pragma unroll
        for (int kc = 0; kc < 4; ++kc) {
            uint32_t ah[4];
            ldsm_x4(ah, sbase + (QH_O)*2 + aoff + kc * 32);
#pragma unroll
            for (int np = 0; np < 4; ++np) {
                uint32_t bhf[4];
                uint32_t boff = (uint32_t)(((np * 16 + brow) * PITCH + kc * 16 + bk) * 2);
                ldsm_x4(bhf, sbase + (KH_O)*2 + boff);
                mma_f16(S[np * 2 + 0], ah, &bhf[0]);
                mma_f16(S[np * 2 + 1], ah, &bhf[2]);
            }
        }

        // causal mask (diagonal tiles only)
        if (kt * 64 + 63 > q0 + wq * 16) {
#pragma unroll
            for (int j = 0; j < 8; ++j) {
                int c0 = kt * 64 + j * 8 + ccol;
                if (c0     > row0) S[j][0] = -30000.0f;
                if (c0 + 1 > row0) S[j][1] = -30000.0f;
                if (c0     > row1) S[j][2] = -30000.0f;
                if (c0 + 1 > row1) S[j][3] = -30000.0f;
            }
        }

        float mt0 = -1e30f, mt1 = -1e30f;
#pragma unroll
        for (int j = 0; j < 8; ++j) {
            mt0 = fmaxf(mt0, fmaxf(S[j][0], S[j][1]));
            mt1 = fmaxf(mt1, fmaxf(S[j][2], S[j][3]));
        }
#pragma unroll
        for (int off = 1; off <= 2; off <<= 1) {
            mt0 = fmaxf(mt0, __shfl_xor_sync(0xffffffffu, mt0, off));
            mt1 = fmaxf(mt1, __shfl_xor_sync(0xffffffffu, mt1, off));
        }
        float mn0 = fmaxf(m0r, mt0), mn1 = fmaxf(m1r, mt1);
        float a0 = ex2f(m0r - mn0), a1 = ex2f(m1r - mn1);
        m0r = mn0; m1r = mn1;
#pragma unroll
        for (int f = 0; f < 10; ++f) {
            O[f][0] *= a0; O[f][1] *= a0;
            O[f][2] *= a1; O[f][3] *= a1;
        }

        // P = exp2(S - m) -> fp16 smem (each warp owns its 16 rows)
        const int prow = wq * 16 + (lane >> 2);
#pragma unroll
        for (int j = 0; j < 8; ++j) {
            float p0 = ex2f(S[j][0] - mn0), p1 = ex2f(S[j][1] - mn0);
            float p2 = ex2f(S[j][2] - mn1), p3 = ex2f(S[j][3] - mn1);
            int c = j * 8 + ccol;
            *(__half2*)&sm[PS_O + prow * PITCH + c]       = __floats2half2_rn(p0, p1);
            *(__half2*)&sm[PS_O + (prow + 8) * PITCH + c] = __floats2half2_rn(p2, p3);
        }
        __syncwarp();

        // O += P * V^T   (n = 80: cols 0..63 ctx, col 64 = l)
#pragma unroll
        for (int kc = 0; kc < 4; ++kc) {
            uint32_t ap[4];
            ldsm_x4(ap, sbase + (PS_O)*2 + aoff + kc * 32);
#pragma unroll
            for (int np = 0; np < 5; ++np) {
                uint32_t bv[4];
                ldsm_x4(bv, sbase + (VT_O)*2 +
                        (uint32_t)(((np * 16 + brow) * PITCH + kc * 16 + bk) * 2));
                mma_f16(O[np * 2 + 0], ap, &bv[0]);
                mma_f16(O[np * 2 + 1], ap, &bv[2]);
            }
        }
    }

    // epilogue: normalize by l (accum col 64), write fp16 ctx [B,S,D]
    float l0 = __shfl_sync(0xffffffffu, O[8][0], lane & ~3);
    float l1 = __shfl_sync(0xffffffffu, O[8][2], lane & ~3);
    float i0 = 1.0f / l0, i1 = 1.0f / l1;
    const int b = bh >> 4, h = bh & 15;
#pragma unroll
    for (int j = 0; j < 8; ++j) {
        int c = h * 64 + j * 8 + ccol;
#pragma unroll
        for (int half_ = 0; half_ < 2; ++half_) {
            int srow = half_ ? row1 : row0;
            float v0 = O[j][half_ * 2 + 0] * (half_ ? i1 : i0);
            float v1 = O[j][half_ * 2 + 1] * (half_ ? i1 : i0);
            *(__half2*)&g_ctxh[((size_t)b * S_ + srow) * D_ + c] =
                __floats2half2_rn(v0, v1);
        }
    }
}

// ---------------------------------------------------------------------------
// Launch
// ---------------------------------------------------------------------------
extern "C" void kernel_launch(void* const* d_in, const int* in_sizes, int n_in,
                              void* d_out, int out_size)
{
    const float* x  = (const float*)d_in[0];
    const float* Wq = (const float*)d_in[1];
    const float* Wk = (const float*)d_in[2];
    const float* Wv = (const float*)d_in[3];
    const float* Wo = (const float*)d_in[4];
    float* out = (float*)d_out;

    cvt_x_kernel<<<(M_ * D_ / 4) / 256, 256>>>((const float4*)x);
    cvt_w_kernel<<<dim3((D_ * D_ / 4) / 256, 4), 256>>>(
        (const float4*)Wq, (const float4*)Wk, (const float4*)Wv, (const float4*)Wo);
    vt_init_kernel<<<(64 * 16 * 2048) / 256, 256>>>();

    // 1) QKV projections (fp16 MMA, K=1024) -> fp16 attention operands
    {
        cudaFuncSetAttribute(mma_gemm_kernel<true>,
                             cudaFuncAttributeMaxDynamicSharedMemorySize, GEMM_SMEM);
        dim3 grid(D_ / 128, M_ / 128, 3);
        mma_gemm_kernel<true><<<grid, 256, GEMM_SMEM>>>(nullptr);
    }

    // 2) MMA flash attention -> g_ctxh (fp16)
    {
        const int smem_bytes = SM_HALVES * 2;   // 57600
        cudaFuncSetAttribute(attn_mma_kernel,
                             cudaFuncAttributeMaxDynamicSharedMemorySize, smem_bytes);
        dim3 grid(B_ * H_, S_ / 128);
        attn_mma_kernel<<<grid, 256, smem_bytes>>>();
    }

    // 3) output projection -> d_out
    {
        cudaFuncSetAttribute(mma_gemm_kernel<false>,
                             cudaFuncAttributeMaxDynamicSharedMemorySize, GEMM_SMEM);
        dim3 grid(D_ / 128, M_ / 128);
        mma_gemm_kernel<false><<<grid, 256, GEMM_SMEM>>>(out);
    }
}

// round 16
// speedup vs baseline: 8.1288x; 1.1992x over previous
#include <cuda_runtime.h>
#include <cuda_bf16.h>
#include <cuda_fp16.h>
#include <cstdint>

// Problem constants
#define B_  4
#define S_  2048
#define D_  1024
#define H_  16
#define HD_ 64
#define M_  (B_*S_)   // 8192
#define NKT 32        // 1024 / 32 k-tiles (single fp16, no split)

#define CQ  0.1803368801111244f   // 0.125 * log2(e): folded into Q

// Scratch (device globals — no allocation allowed)
__device__ __half g_qh[(size_t)B_*H_*S_*HD_];   // Q*CQ  [B,H,S,64] fp16
__device__ __half g_kh[(size_t)B_*H_*S_*HD_];   // K     [B,H,S,64] fp16
__device__ __half g_vt[(size_t)B_*H_*80*S_];    // V^T [B,H,80,S]; row64=1, 65..79=0
__device__ __half g_xh[(size_t)M_*D_];          // x fp16
__device__ __half g_ctxh[(size_t)M_*D_];        // ctx fp16
__device__ __half g_wh[4][(size_t)D_*D_];       // Wq,Wk,Wv,Wo fp16

// ---------------------------------------------------------------------------
// PTX helpers
// ---------------------------------------------------------------------------
__device__ __forceinline__ void cp_async16(uint32_t s, const void* g) {
    asm volatile("cp.async.cg.shared.global [%0], [%1], 16;\n" :: "r"(s), "l"(g));
}
__device__ __forceinline__ void cp_commit() {
    asm volatile("cp.async.commit_group;\n");
}
__device__ __forceinline__ void ldsm_x4(uint32_t* r, uint32_t addr) {
    asm volatile("ldmatrix.sync.aligned.m8n8.x4.shared.b16 {%0,%1,%2,%3}, [%4];\n"
        : "=r"(r[0]), "=r"(r[1]), "=r"(r[2]), "=r"(r[3]) : "r"(addr));
}
__device__ __forceinline__ void mma_f16(float* c, const uint32_t* a, const uint32_t* b) {
    asm volatile("mma.sync.aligned.m16n8k16.row.col.f32.f16.f16.f32 "
        "{%0,%1,%2,%3}, {%4,%5,%6,%7}, {%8,%9}, {%0,%1,%2,%3};\n"
        : "+f"(c[0]), "+f"(c[1]), "+f"(c[2]), "+f"(c[3])
        : "r"(a[0]), "r"(a[1]), "r"(a[2]), "r"(a[3]), "r"(b[0]), "r"(b[1]));
}
__device__ __forceinline__ float ex2f(float x) {
    float r;
    asm("ex2.approx.ftz.f32 %0, %1;" : "=f"(r) : "f"(x));
    return r;
}
__device__ __forceinline__ uint32_t packh2(float a, float b) {
    __half2 h = __floats2half2_rn(a, b);
    return *(uint32_t*)&h;
}

// ---------------------------------------------------------------------------
// Convert kernels: fp32 -> fp16 (linear layouts)
// ---------------------------------------------------------------------------
__device__ __forceinline__ ushort4 cvt4(float4 v) {
    return make_ushort4(__half_as_ushort(__float2half_rn(v.x)),
                        __half_as_ushort(__float2half_rn(v.y)),
                        __half_as_ushort(__float2half_rn(v.z)),
                        __half_as_ushort(__float2half_rn(v.w)));
}

__global__ __launch_bounds__(256) void cvt_x_kernel(const float4* __restrict__ x4) {
    int i = blockIdx.x * 256 + threadIdx.x;
    *(ushort4*)&g_xh[(size_t)i * 4] = cvt4(x4[i]);
}

__global__ __launch_bounds__(256) void cvt_w_kernel(
    const float4* __restrict__ Wq4, const float4* __restrict__ Wk4,
    const float4* __restrict__ Wv4, const float4* __restrict__ Wo4)
{
    int which = blockIdx.y;
    const float4* src = (which == 0) ? Wq4 : (which == 1) ? Wk4 : (which == 2) ? Wv4 : Wo4;
    int i = blockIdx.x * 256 + threadIdx.x;
    *(ushort4*)&g_wh[which][(size_t)i * 4] = cvt4(src[i]);
}

__global__ __launch_bounds__(256) void vt_init_kernel() {
    size_t i = (size_t)blockIdx.x * 256 + threadIdx.x;  // 64 * 16 * 2048
    int bh  = (int)(i >> 15);
    int rem = (int)(i & 32767);
    int r   = rem >> 11;
    int s   = rem & 2047;
    g_vt[((size_t)bh * 80 + 64 + r) * S_ + s] = __float2half((r == 0) ? 1.0f : 0.0f);
}

// ---------------------------------------------------------------------------
// fp16 MMA GEMM (verified R15): K=1024, 4-stage cp.async, 128x128 block.
// ---------------------------------------------------------------------------
#define SPITCH  40
#define CH2     (64*SPITCH*2)
#define ST      4
#define STAGE_B (128*SPITCH*2)
#define GEMM_SMEM (ST*STAGE_B*2)

template<bool PERM>
__global__ __launch_bounds__(256, 2) void mma_gemm_kernel(float* __restrict__ outp)
{
    extern __shared__ __half dsm[];

    const __half* A;
    const __half* W;
    if (PERM) { A = g_xh;   W = g_wh[blockIdx.z]; }
    else      { A = g_ctxh; W = g_wh[3]; }

    const int tid  = threadIdx.x;
    const int lane = tid & 31;
    const int wid  = tid >> 5;
    const int wm   = wid & 1;
    const int wn   = wid >> 1;
    const int m0   = blockIdx.y * 128;
    const int n0   = blockIdx.x * 128;

    const int c0r = tid >> 2;
    const int c0c = (tid & 3) * 8;

    const uint32_t aS = (uint32_t)__cvta_generic_to_shared(dsm);
    const uint32_t bS = aS + ST * STAGE_B;
    const uint32_t stA0 = aS + (uint32_t)(c0r * SPITCH + c0c) * 2;
    const uint32_t stB0 = bS + (uint32_t)(c0r * SPITCH + c0c) * 2;

    const int a_row = wm * 64 + (lane & 15);
    const int a_k   = (lane >> 4) * 8;
    const int b_row = wn * 32 + (lane & 7) + ((lane & 16) ? 8 : 0);
    const int b_k   = (lane & 8) ? 8 : 0;

    float acc[4][4][4];
#pragma unroll
    for (int mi = 0; mi < 4; ++mi)
#pragma unroll
        for (int nt = 0; nt < 4; ++nt)
#pragma unroll
            for (int r = 0; r < 4; ++r) acc[mi][nt][r] = 0.0f;

    auto issue = [&](int kt, int buf) {
        int koff = kt * 32;
        uint32_t sa = stA0 + (uint32_t)buf * STAGE_B;
        uint32_t sb = stB0 + (uint32_t)buf * STAGE_B;
        cp_async16(sa,       A + (size_t)(m0 + c0r) * D_ + koff + c0c);
        cp_async16(sa + CH2, A + (size_t)(m0 + c0r + 64) * D_ + koff + c0c);
        cp_async16(sb,       W + (size_t)(n0 + c0r) * D_ + koff + c0c);
        cp_async16(sb + CH2, W + (size_t)(n0 + c0r + 64) * D_ + koff + c0c);
        cp_commit();
    };

    issue(0, 0);
    issue(1, 1);
    issue(2, 2);

    for (int kt = 0; kt < NKT; ++kt) {
        const int cur = kt & 3;
        if (kt < NKT - 2)      asm volatile("cp.async.wait_group 2;\n");
        else if (kt == NKT-2)  asm volatile("cp.async.wait_group 1;\n");
        else                   asm volatile("cp.async.wait_group 0;\n");
        __syncthreads();

        if (kt + 3 < NKT) issue(kt + 3, (kt + 3) & 3);

        const uint32_t smA_cur = aS + (uint32_t)cur * STAGE_B;
        const uint32_t smB_cur = bS + (uint32_t)cur * STAGE_B;
#pragma unroll
        for (int kk = 0; kk < 32; kk += 16) {
            uint32_t af[4][4], bfr[2][4];
#pragma unroll
            for (int mi = 0; mi < 4; ++mi)
                ldsm_x4(af[mi], smA_cur + ((a_row + mi * 16) * SPITCH + kk + a_k) * 2);
#pragma unroll
            for (int np = 0; np < 2; ++np)
                ldsm_x4(bfr[np], smB_cur + ((b_row + np * 16) * SPITCH + kk + b_k) * 2);
#pragma unroll
            for (int mi = 0; mi < 4; ++mi)
#pragma unroll
                for (int nt = 0; nt < 4; ++nt)
                    mma_f16(acc[mi][nt], af[mi], &bfr[nt >> 1][(nt & 1) * 2]);
        }
    }

    const int tr = lane >> 2;
    const int tc = (lane & 3) * 2;
#pragma unroll
    for (int mi = 0; mi < 4; ++mi) {
#pragma unroll
        for (int ni = 0; ni < 4; ++ni) {
            int r = m0 + wm * 64 + mi * 16 + tr;
            int c = n0 + wn * 32 + ni * 8 + tc;
#pragma unroll
            for (int half_ = 0; half_ < 2; ++half_) {
                int m = r + half_ * 8;
                float v0 = acc[mi][ni][half_ * 2 + 0];
                float v1 = acc[mi][ni][half_ * 2 + 1];
                if (PERM) {
                    int b  = m >> 11;
                    int s  = m & (S_ - 1);
                    int hh = c >> 6;
                    int hd = c & 63;
                    size_t bh = (size_t)(b * H_ + hh);
                    if (blockIdx.z == 2) {
                        size_t base = (bh * 80 + hd) * S_ + s;
                        g_vt[base]      = __float2half_rn(v0);
                        g_vt[base + S_] = __float2half_rn(v1);
                    } else {
                        __half* dh = (blockIdx.z == 0) ? g_qh : g_kh;
                        if (blockIdx.z == 0) { v0 *= CQ; v1 *= CQ; }
                        size_t idx = (bh * S_ + s) * 64 + hd;
                        *(__half2*)&dh[idx] = __floats2half2_rn(v0, v1);
                    }
                } else {
                    *(float2*)&outp[(size_t)m * D_ + c] = make_float2(v0, v1);
                }
            }
        }
    }
}

// ---------------------------------------------------------------------------
// MMA flash attention (causal). Block = (bh, 128-row q-tile); 8 warps x 16 rows.
// P kept in registers (S C-frag -> PV A-frag identity); K/V double-buffered
// via cp.async. smem: Q[128x72] + 2 x {K 64x72, V 80x72} = 59904 B.
// ---------------------------------------------------------------------------
#define PITCH 72
#define Q_O   0
#define ST_H  (144*PITCH)                  // halves per K/V stage
#define K_OFF(b) (128*PITCH + (b)*ST_H)
#define V_OFF(b) (K_OFF(b) + 64*PITCH)
#define SM_HALVES (128*PITCH + 2*ST_H)     // 29952 halves = 59904 B

__global__ __launch_bounds__(256, 2) void attn_mma_kernel()
{
    extern __shared__ __half sm[];
    const uint32_t sbase = (uint32_t)__cvta_generic_to_shared(sm);

    const int bh  = blockIdx.x;
    const int qt  = 15 - blockIdx.y;      // heavy tiles first
    const int q0  = qt * 128;
    const int tid = threadIdx.x;
    const int lane = tid & 31;
    const int wq   = tid >> 5;

    const __half* gQh = g_qh + (size_t)bh * S_ * 64;
    const __half* gKh = g_kh + (size_t)bh * S_ * 64;
    const __half* gVt = g_vt + (size_t)bh * 80 * S_;

    // Q tile (plain vector loads; first barrier publishes)
    for (int i = tid; i < 128 * 8; i += 256) {
        int r = i >> 3, ch = (i & 7) * 8;
        *(float4*)&sm[Q_O + r * PITCH + ch] = *(const float4*)&gQh[(size_t)(q0 + r) * 64 + ch];
    }

    // cp.async staging geometry (one 16B chunk per (row, col8) slot)
    const int lr = tid >> 3;           // 0..31
    const int lc = (tid & 7) * 8;      // half offset
    auto issue_kv = [&](int kt, int buf) {
        uint32_t kb = sbase + (uint32_t)(K_OFF(buf)) * 2;
        uint32_t vb = sbase + (uint32_t)(V_OFF(buf)) * 2;
#pragma unroll
        for (int j = 0; j < 2; ++j) {   // K rows lr, lr+32
            int r = lr + j * 32;
            cp_async16(kb + (uint32_t)(r * PITCH + lc) * 2,
                       gKh + (size_t)(kt * 64 + r) * 64 + lc);
        }
#pragma unroll
        for (int j = 0; j < 3; ++j) {   // V rows lr, lr+32, lr+64 (<80)
            int r = lr + j * 32;
            if (r < 80)
                cp_async16(vb + (uint32_t)(r * PITCH + lc) * 2,
                           gVt + (size_t)r * S_ + kt * 64 + lc);
        }
        cp_commit();
    };

    float O[10][4];
#pragma unroll
    for (int f = 0; f < 10; ++f)
#pragma unroll
        for (int r = 0; r < 4; ++r) O[f][r] = 0.0f;
    float m0r = -1e30f, m1r = -1e30f;

    const int row0 = q0 + wq * 16 + (lane >> 2);
    const int row1 = row0 + 8;
    const int ccol = (lane & 3) * 2;

    const uint32_t aoff = ((wq * 16 + (lane & 15)) * PITCH + (lane >> 4) * 8) * 2;
    const int brow = (lane & 7) + ((lane & 16) ? 8 : 0);
    const int bk   = (lane & 8) ? 8 : 0;

    const int nkt = 2 * qt + 2;
    issue_kv(0, 0);
    for (int kt = 0; kt < nkt; ++kt) {
        const int cur = kt & 1;
        asm volatile("cp.async.wait_group 0;\n");
        __syncthreads();   // buffer cur filled; everyone done reading cur^1
        if (kt + 1 < nkt) issue_kv(kt + 1, cur ^ 1);

        if (kt * 64 > q0 + wq * 16 + 15) continue;   // whole warp masked

        const uint32_t kS = sbase + (uint32_t)(K_OFF(cur)) * 2;
        const uint32_t vS = sbase + (uint32_t)(V_OFF(cur)) * 2;

        // S = Q K^T  (log2 domain; scale folded into Q)
        float S[8][4];
#pragma unroll
        for (int j = 0; j < 8; ++j)
#pragma unroll
            for (int r = 0; r < 4; ++r) S[j][r] = 0.0f;

#pragma unroll
        for (int kc = 0; kc < 4; ++kc) {
            uint32_t ah[4];
            ldsm_x4(ah, sbase + (Q_O)*2 + aoff + kc * 32);
#pragma unroll
            for (int np = 0; np < 4; ++np) {
                uint32_t bhf[4];
                ldsm_x4(bhf, kS + (uint32_t)(((np * 16 + brow) * PITCH + kc * 16 + bk) * 2));
                mma_f16(S[np * 2 + 0], ah, &bhf[0]);
                mma_f16(S[np * 2 + 1], ah, &bhf[2]);
            }
        }

        // causal mask (diagonal tiles only)
        if (kt * 64 + 63 > q0 + wq * 16) {
#pragma unroll
            for (int j = 0; j < 8; ++j) {
                int c0 = kt * 64 + j * 8 + ccol;
                if (c0     > row0) S[j][0] = -30000.0f;
                if (c0 + 1 > row0) S[j][1] = -30000.0f;
                if (c0     > row1) S[j][2] = -30000.0f;
                if (c0 + 1 > row1) S[j][3] = -30000.0f;
            }
        }

        // online softmax (row max across frags, then across quad lanes)
        float mt0 = -1e30f, mt1 = -1e30f;
#pragma unroll
        for (int j = 0; j < 8; ++j) {
            mt0 = fmaxf(mt0, fmaxf(S[j][0], S[j][1]));
            mt1 = fmaxf(mt1, fmaxf(S[j][2], S[j][3]));
        }
#pragma unroll
        for (int off = 1; off <= 2; off <<= 1) {
            mt0 = fmaxf(mt0, __shfl_xor_sync(0xffffffffu, mt0, off));
            mt1 = fmaxf(mt1, __shfl_xor_sync(0xffffffffu, mt1, off));
        }
        float mn0 = fmaxf(m0r, mt0), mn1 = fmaxf(m1r, mt1);
        float a0 = ex2f(m0r - mn0), a1 = ex2f(m1r - mn1);
        m0r = mn0; m1r = mn1;
#pragma unroll
        for (int f = 0; f < 10; ++f) {
            O[f][0] *= a0; O[f][1] *= a0;
            O[f][2] *= a1; O[f][3] *= a1;
        }

        // P = exp2(S - m), packed straight into PV A-fragments (registers only):
        // A-frag k-chunk kc: reg0 = S[2kc]{c0,c1}, reg1 = S[2kc]{c2,c3},
        //                    reg2 = S[2kc+1]{c0,c1}, reg3 = S[2kc+1]{c2,c3}.
        uint32_t ap[4][4];
#pragma unroll
        for (int kc = 0; kc < 4; ++kc) {
            int j0 = 2 * kc, j1 = 2 * kc + 1;
            ap[kc][0] = packh2(ex2f(S[j0][0] - mn0), ex2f(S[j0][1] - mn0));
            ap[kc][1] = packh2(ex2f(S[j0][2] - mn1), ex2f(S[j0][3] - mn1));
            ap[kc][2] = packh2(ex2f(S[j1][0] - mn0), ex2f(S[j1][1] - mn0));
            ap[kc][3] = packh2(ex2f(S[j1][2] - mn1), ex2f(S[j1][3] - mn1));
        }

        // O += P * V^T   (n = 80: cols 0..63 ctx, col 64 = l)
#pragma unroll
        for (int kc = 0; kc < 4; ++kc) {
#pragma unroll
            for (int np = 0; np < 5; ++np) {
                uint32_t bv[4];
                ldsm_x4(bv, vS + (uint32_t)(((np * 16 + brow) * PITCH + kc * 16 + bk) * 2));
                mma_f16(O[np * 2 + 0], ap[kc], &bv[0]);
                mma_f16(O[np * 2 + 1], ap[kc], &bv[2]);
            }
        }
    }

    // epilogue: normalize by l (accum col 64), write fp16 ctx [B,S,D]
    float l0 = __shfl_sync(0xffffffffu, O[8][0], lane & ~3);
    float l1 = __shfl_sync(0xffffffffu, O[8][2], lane & ~3);
    float i0 = 1.0f / l0, i1 = 1.0f / l1;
    const int b = bh >> 4, h = bh & 15;
#pragma unroll
    for (int j = 0; j < 8; ++j) {
        int c = h * 64 + j * 8 + ccol;
#pragma unroll
        for (int half_ = 0; half_ < 2; ++half_) {
            int srow = half_ ? row1 : row0;
            float v0 = O[j][half_ * 2 + 0] * (half_ ? i1 : i0);
            float v1 = O[j][half_ * 2 + 1] * (half_ ? i1 : i0);
            *(__half2*)&g_ctxh[((size_t)b * S_ + srow) * D_ + c] =
                __floats2half2_rn(v0, v1);
        }
    }
}

// ---------------------------------------------------------------------------
// Launch
// ---------------------------------------------------------------------------
extern "C" void kernel_launch(void* const* d_in, const int* in_sizes, int n_in,
                              void* d_out, int out_size)
{
    const float* x  = (const float*)d_in[0];
    const float* Wq = (const float*)d_in[1];
    const float* Wk = (const float*)d_in[2];
    const float* Wv = (const float*)d_in[3];
    const float* Wo = (const float*)d_in[4];
    float* out = (float*)d_out;

    cvt_x_kernel<<<(M_ * D_ / 4) / 256, 256>>>((const float4*)x);
    cvt_w_kernel<<<dim3((D_ * D_ / 4) / 256, 4), 256>>>(
        (const float4*)Wq, (const float4*)Wk, (const float4*)Wv, (const float4*)Wo);
    vt_init_kernel<<<(64 * 16 * 2048) / 256, 256>>>();

    // 1) QKV projections (fp16 MMA, K=1024) -> fp16 attention operands
    {
        cudaFuncSetAttribute(mma_gemm_kernel<true>,
                             cudaFuncAttributeMaxDynamicSharedMemorySize, GEMM_SMEM);
        dim3 grid(D_ / 128, M_ / 128, 3);
        mma_gemm_kernel<true><<<grid, 256, GEMM_SMEM>>>(nullptr);
    }

    // 2) MMA flash attention -> g_ctxh (fp16)
    {
        const int smem_bytes = SM_HALVES * 2;   // 59904
        cudaFuncSetAttribute(attn_mma_kernel,
                             cudaFuncAttributeMaxDynamicSharedMemorySize, smem_bytes);
        dim3 grid(B_ * H_, S_ / 128);
        attn_mma_kernel<<<grid, 256, smem_bytes>>>();
    }

    // 3) output projection -> d_out
    {
        cudaFuncSetAttribute(mma_gemm_kernel<false>,
                             cudaFuncAttributeMaxDynamicSharedMemorySize, GEMM_SMEM);
        dim3 grid(D_ / 128, M_ / 128);
        mma_gemm_kernel<false><<<grid, 256, GEMM_SMEM>>>(out);
    }
}